// round 11
// baseline (speedup 1.0000x reference)
#include <cuda_runtime.h>
#include <cuda_bf16.h>
#include <cstdint>

// orig_fea [256, 300, 256] f32; ind0/ind1 [32,32,4] i32; W1a/W1b [256,256];
// b1[256]; W2[256,1]; b2[1]. L=128, pool=1200.
#define LN   128
#define DD   256
#define HH   256
#define NUMG 32
#define BAG  300

typedef unsigned long long u64;

// Scratch: h0/h1 transposed: [side][n][h][a]  (8 MB)
__device__ float g_hT[2][NUMG][HH][LN];

// ============================ helpers ============================
__device__ __forceinline__ uint32_t smem_u32(const void* p) {
    uint32_t a;
    asm("{ .reg .u64 t; cvta.to.shared.u64 t, %1; cvt.u32.u64 %0, t; }"
        : "=r"(a) : "l"(p));
    return a;
}
__device__ __forceinline__ u64 pack2(float lo, float hi) {
    u64 r; asm("mov.b64 %0, {%1,%2};" : "=l"(r) : "f"(lo), "f"(hi)); return r;
}
__device__ __forceinline__ float2 unpk2(u64 v) {
    float2 r; asm("mov.b64 {%0,%1}, %2;" : "=f"(r.x), "=f"(r.y) : "l"(v)); return r;
}
__device__ __forceinline__ u64 add2(u64 a, u64 b) {
    u64 r; asm("add.rn.f32x2 %0, %1, %2;" : "=l"(r) : "l"(a), "l"(b)); return r;
}
__device__ __forceinline__ u64 fma2(u64 a, u64 b, u64 c) {
    u64 r; asm("fma.rn.f32x2 %0, %1, %2, %3;" : "=l"(r) : "l"(a), "l"(b), "l"(c)); return r;
}
// f32 pair -> bf16x2 (low half = x0); also return rounded values as f32
__device__ __forceinline__ uint32_t cvt_pair(float x0, float x1, float& h0f, float& h1f) {
    uint32_t r;
    asm("cvt.rn.bf16x2.f32 %0, %1, %2;" : "=r"(r) : "f"(x1), "f"(x0));
    h0f = __uint_as_float(r << 16);
    h1f = __uint_as_float(r & 0xFFFF0000u);
    return r;
}
__device__ __forceinline__ uint32_t cvt_pair_n(float x0, float x1) {
    uint32_t r;
    asm("cvt.rn.bf16x2.f32 %0, %1, %2;" : "=r"(r) : "f"(x1), "f"(x0));
    return r;
}
__device__ __forceinline__ void ldsm4(uint32_t* r, uint32_t addr) {
    asm volatile("ldmatrix.sync.aligned.m8n8.x4.shared.b16 {%0,%1,%2,%3}, [%4];"
        : "=r"(r[0]), "=r"(r[1]), "=r"(r[2]), "=r"(r[3]) : "r"(addr));
}
__device__ __forceinline__ void ldsm4t(uint32_t* r, uint32_t addr) {
    asm volatile("ldmatrix.sync.aligned.m8n8.x4.trans.shared.b16 {%0,%1,%2,%3}, [%4];"
        : "=r"(r[0]), "=r"(r[1]), "=r"(r[2]), "=r"(r[3]) : "r"(addr));
}
__device__ __forceinline__ void mma16816(float* d, const uint32_t* a,
                                         uint32_t b0, uint32_t b1) {
    asm volatile("mma.sync.aligned.m16n8k16.row.col.f32.bf16.bf16.f32 "
        "{%0,%1,%2,%3}, {%4,%5,%6,%7}, {%8,%9}, {%0,%1,%2,%3};"
        : "+f"(d[0]), "+f"(d[1]), "+f"(d[2]), "+f"(d[3])
        : "r"(a[0]), "r"(a[1]), "r"(a[2]), "r"(a[3]), "r"(b0), "r"(b1));
}
// XOR swizzle: rows of 128B, 16B atoms permuted by row%8 -> conflict-free LDSM
#define SWZ(row, kb) ((row) * 128 + ((kb) ^ (((row) & 7) << 4)))

// ---------------------------------------------------------------------------
// Kernel 1: mma.sync bf16 split-precision GEMM (UNCHANGED from R8/R10).
// ---------------------------------------------------------------------------
__global__ __launch_bounds__(256)
void gemm_mma_kernel(const float* __restrict__ orig,
                     const int*   __restrict__ ind0,
                     const int*   __restrict__ ind1,
                     const float* __restrict__ W1a,
                     const float* __restrict__ W1b,
                     const float* __restrict__ bias1)
{
    extern __shared__ char dsm[];
    __shared__ int rowoff[128];

    const int t = threadIdx.x, l = t & 31, w = t >> 5;
    const int b    = blockIdx.x;
    const int side = b >> 7;
    const int n    = (b >> 2) & 31;
    const int h0   = (b & 3) * 64;
    const int m0   = (w & 3) * 32;
    const int n0   = (w >> 2) * 32;
    const float* __restrict__ Wmat = side ? W1b : W1a;

    const uint32_t smb = smem_u32(dsm);
    const int offAhi = 0, offAlo = 16384, offBhi = 32768, offBlo = 40960;

    if (t < 128) {
        const int* __restrict__ ind = side ? ind1 : ind0;
        int p = ind[n * LN + t] + BAG * (t & 3);
        rowoff[t] = ((n * 2 + side) * 1200 + p) * DD;
    }
    __syncthreads();

    const int arow  = t >> 1;
    const int halfk = t & 1;
    const int ro    = rowoff[arow];
    const int bkr   = t >> 2;
    const int bhq   = t & 3;

    float acc[2][4][4];
#pragma unroll
    for (int mt = 0; mt < 2; mt++)
#pragma unroll
        for (int nt = 0; nt < 4; nt++)
#pragma unroll
            for (int i = 0; i < 4; i++) acc[mt][nt][i] = 0.f;

#pragma unroll 1
    for (int c = 0; c < 4; c++) {
        {
            const float4* ap = (const float4*)(orig + ro + c * 64 + halfk * 32);
            float4 av[8];
#pragma unroll
            for (int q = 0; q < 8; q++) av[q] = ap[q];
#pragma unroll
            for (int q2 = 0; q2 < 4; q2++) {
                float4 u = av[2 * q2], v = av[2 * q2 + 1];
                float r0, r1, r2, r3, r4, r5, r6, r7;
                uint32_t hp0 = cvt_pair(u.x, u.y, r0, r1);
                uint32_t hp1 = cvt_pair(u.z, u.w, r2, r3);
                uint32_t hp2 = cvt_pair(v.x, v.y, r4, r5);
                uint32_t hp3 = cvt_pair(v.z, v.w, r6, r7);
                uint32_t lp0 = cvt_pair_n(u.x - r0, u.y - r1);
                uint32_t lp1 = cvt_pair_n(u.z - r2, u.w - r3);
                uint32_t lp2 = cvt_pair_n(v.x - r4, v.y - r5);
                uint32_t lp3 = cvt_pair_n(v.z - r6, v.w - r7);
                int kb = halfk * 64 + q2 * 16;
                *(uint4*)(dsm + offAhi + SWZ(arow, kb)) = make_uint4(hp0, hp1, hp2, hp3);
                *(uint4*)(dsm + offAlo + SWZ(arow, kb)) = make_uint4(lp0, lp1, lp2, lp3);
            }
        }
        {
            const float4* wp = (const float4*)&Wmat[(c * 64 + bkr) * HH + h0 + bhq * 16];
            float4 wv[4];
#pragma unroll
            for (int q = 0; q < 4; q++) wv[q] = wp[q];
            uint32_t hi[8], lo[8];
#pragma unroll
            for (int q2 = 0; q2 < 2; q2++) {
                float4 u = wv[2 * q2], v = wv[2 * q2 + 1];
                float r0, r1, r2, r3, r4, r5, r6, r7;
                hi[q2 * 4 + 0] = cvt_pair(u.x, u.y, r0, r1);
                hi[q2 * 4 + 1] = cvt_pair(u.z, u.w, r2, r3);
                hi[q2 * 4 + 2] = cvt_pair(v.x, v.y, r4, r5);
                hi[q2 * 4 + 3] = cvt_pair(v.z, v.w, r6, r7);
                lo[q2 * 4 + 0] = cvt_pair_n(u.x - r0, u.y - r1);
                lo[q2 * 4 + 1] = cvt_pair_n(u.z - r2, u.w - r3);
                lo[q2 * 4 + 2] = cvt_pair_n(v.x - r4, v.y - r5);
                lo[q2 * 4 + 3] = cvt_pair_n(v.z - r6, v.w - r7);
            }
            int kb = bhq * 32;
            *(uint4*)(dsm + offBhi + SWZ(bkr, kb))      = make_uint4(hi[0], hi[1], hi[2], hi[3]);
            *(uint4*)(dsm + offBhi + SWZ(bkr, kb + 16)) = make_uint4(hi[4], hi[5], hi[6], hi[7]);
            *(uint4*)(dsm + offBlo + SWZ(bkr, kb))      = make_uint4(lo[0], lo[1], lo[2], lo[3]);
            *(uint4*)(dsm + offBlo + SWZ(bkr, kb + 16)) = make_uint4(lo[4], lo[5], lo[6], lo[7]);
        }
        __syncthreads();

#pragma unroll
        for (int ks = 0; ks < 4; ks++) {
            const int rA  = m0 + (l & 15);
            const int kbL = ks * 32 + ((l >> 4) << 4);
            uint32_t ahi[2][4], alo[2][4], bhi[2][4], blo[2][4];
            ldsm4(ahi[0], smb + offAhi + SWZ(rA, kbL));
            ldsm4(ahi[1], smb + offAhi + SWZ(rA + 16, kbL));
            ldsm4(alo[0], smb + offAlo + SWZ(rA, kbL));
            ldsm4(alo[1], smb + offAlo + SWZ(rA + 16, kbL));
            const int rK = ks * 16 + (l & 15);
            const int hb = ((l >> 4) << 4);
            ldsm4t(bhi[0], smb + offBhi + SWZ(rK, n0 * 2 + hb));
            ldsm4t(bhi[1], smb + offBhi + SWZ(rK, n0 * 2 + 32 + hb));
            ldsm4t(blo[0], smb + offBlo + SWZ(rK, n0 * 2 + hb));
            ldsm4t(blo[1], smb + offBlo + SWZ(rK, n0 * 2 + 32 + hb));
#pragma unroll
            for (int mt = 0; mt < 2; mt++)
#pragma unroll
                for (int g = 0; g < 2; g++)
#pragma unroll
                    for (int s = 0; s < 2; s++) {
                        int nt = g * 2 + s;
                        mma16816(acc[mt][nt], ahi[mt], bhi[g][2 * s], bhi[g][2 * s + 1]);
                        mma16816(acc[mt][nt], alo[mt], bhi[g][2 * s], bhi[g][2 * s + 1]);
                        mma16816(acc[mt][nt], ahi[mt], blo[g][2 * s], blo[g][2 * s + 1]);
                    }
        }
        __syncthreads();
    }

    const int g    = l >> 2;
    const int tid4 = l & 3;
#pragma unroll
    for (int mt = 0; mt < 2; mt++) {
        int ag = m0 + mt * 16 + g;
#pragma unroll
        for (int nt = 0; nt < 4; nt++) {
            int hg = h0 + n0 + nt * 8 + tid4 * 2;
            float bv0 = 0.f, bv1 = 0.f;
            if (side == 0) { bv0 = __ldg(&bias1[hg]); bv1 = __ldg(&bias1[hg + 1]); }
            g_hT[side][n][hg    ][ag    ] = acc[mt][nt][0] + bv0;
            g_hT[side][n][hg + 1][ag    ] = acc[mt][nt][1] + bv1;
            g_hT[side][n][hg    ][ag + 8] = acc[mt][nt][2] + bv0;
            g_hT[side][n][hg + 1][ag + 8] = acc[mt][nt][3] + bv1;
        }
    }
}

// ---------------------------------------------------------------------------
// Kernel 2: R10 structure, inner loop moved to packed f32x2 (FADD2/FFMA2).
// relu(s)*w == (s + |s|) * (0.5*w): s+|s| exact; abs via 64-bit AND (alu);
// y pairs come free from the float4 layout; x dup'd in registers.
// grid 512 = n(32) x a-tile(8, 16 a) x b-tile(2, 64 b); block 256:
//   tx = t&15 (patch col), ty = (t>>4)&3 (patch row), th = t>>6 (h mod 4).
// ---------------------------------------------------------------------------
__global__ __launch_bounds__(256)
void pairwise_kernel(const float* __restrict__ W2,
                     const float* __restrict__ b2,
                     float* __restrict__ out,
                     int write_pairs)
{
    const int bid = blockIdx.x;
    const int n   = bid >> 4;
    const int at  = (bid >> 1) & 7;
    const int bt  = bid & 1;
    const int a0  = at * 16;
    const int b0  = bt * 64;
    const int t   = threadIdx.x;
    const int tx  = t & 15;
    const int ty  = (t >> 4) & 3;
    const int th  = t >> 6;

    __shared__ float4 xs4[256][4];       // [h][a-quad]  16KB
    __shared__ float4 ys4[2][32][16];    // [buf][h][b-quad]  16KB
    __shared__ u64    ws2[256];          // {0.5*W2, 0.5*W2}  2KB

#pragma unroll
    for (int r = 0; r < 4; r++) {
        int id = t + 256 * r;
        int hh = id >> 2, q = id & 3;
        xs4[hh][q] = *(const float4*)&g_hT[0][n][hh][a0 + q * 4];
    }
#pragma unroll
    for (int r = 0; r < 2; r++) {
        int id = t + 256 * r;
        int hh = id >> 4, q = id & 15;
        ys4[0][hh][q] = *(const float4*)&g_hT[1][n][hh][b0 + q * 4];
    }
    {
        float wh = 0.5f * W2[t];
        ws2[t] = pack2(wh, wh);
    }
    __syncthreads();

    u64 acc2[4][2];
#pragma unroll
    for (int j = 0; j < 4; j++) { acc2[j][0] = 0ULL; acc2[j][1] = 0ULL; }

    const u64 ABSM = 0x7FFFFFFF7FFFFFFFULL;

    int buf = 0;
#pragma unroll 1
    for (int hc = 0; hc < 8; hc++) {
        float4 st[2];
        if (hc < 7) {
#pragma unroll
            for (int r = 0; r < 2; r++) {
                int id = t + 256 * r;
                int hh = id >> 4, q = id & 15;
                st[r] = *(const float4*)&g_hT[1][n][(hc + 1) * 32 + hh][b0 + q * 4];
            }
        }
#pragma unroll
        for (int u = 0; u < 8; u++) {
            int hh = th + u * 4;
            int hs = hc * 32 + hh;
            u64 wv2 = ws2[hs];
            float4 x4 = xs4[hs][ty];
            ulonglong2 yv = *(const ulonglong2*)&ys4[buf][hh][tx];
            u64 yy[2] = {yv.x, yv.y};
            float xa[4] = {x4.x, x4.y, x4.z, x4.w};
#pragma unroll
            for (int j = 0; j < 4; j++) {
                u64 xd = pack2(xa[j], xa[j]);
#pragma unroll
                for (int i2 = 0; i2 < 2; i2++) {
                    u64 s  = add2(xd, yy[i2]);
                    u64 uu = add2(s, s & ABSM);     // s + |s| (exact)
                    acc2[j][i2] = fma2(uu, wv2, acc2[j][i2]);
                }
            }
        }
        if (hc < 7) {
            int nb = buf ^ 1;
#pragma unroll
            for (int r = 0; r < 2; r++) {
                int id = t + 256 * r;
                int hh = id >> 4, q = id & 15;
                ys4[nb][hh][q] = st[r];
            }
            __syncthreads();
            buf = nb;
        }
    }

    // unpack to scalar partials, then 4-way reduction in dead xs region
    float acc[4][4];
#pragma unroll
    for (int j = 0; j < 4; j++) {
        float2 p0 = unpk2(acc2[j][0]);
        float2 p1 = unpk2(acc2[j][1]);
        acc[j][0] = p0.x; acc[j][1] = p0.y;
        acc[j][2] = p1.x; acc[j][3] = p1.y;
    }

    float* red = (float*)&xs4[0][0];
    const int p = ty * 16 + tx;   // 0..63
    __syncthreads();
    if (th > 0) {
        int base = ((th - 1) * 64 + p) * 16;
#pragma unroll
        for (int j = 0; j < 4; j++)
#pragma unroll
            for (int i = 0; i < 4; i++) {
                int idx = j * 4 + i;
                red[base + ((idx + p) & 15)] = acc[j][i];
            }
    }
    __syncthreads();
    if (th == 0) {
        float s = 0.f;
#pragma unroll
        for (int j = 0; j < 4; j++)
#pragma unroll
            for (int i = 0; i < 4; i++) s += acc[j][i];
#pragma unroll
        for (int g = 0; g < 3; g++) {
            int base = (g * 64 + p) * 16;
#pragma unroll
            for (int idx = 0; idx < 16; idx++)
                s += red[base + ((idx + p) & 15)];
        }
        s += 16.f * __ldg(b2);
        const int m = at * 4 + ty;
        const int lcol = bt * 16 + tx;
        out[n * 1024 + m * 32 + lcol] = s;
    }

    if (write_pairs && t < 128) {
        int id    = bid * 128 + t;   // 0..65535
        int pi    = id >> 1;
        int which = id & 1;
        int idx   = pi & 1023;
        int v = which ? (idx & 31) : (idx >> 5);
        out[NUMG * 1024 + id] = (float)v;
    }
}

extern "C" void kernel_launch(void* const* d_in, const int* in_sizes, int n_in,
                              void* d_out, int out_size)
{
    const float* orig = (const float*)d_in[0];
    const int*   ind0 = (const int*)d_in[1];
    const int*   ind1 = (const int*)d_in[2];
    int i = 3;
    if (n_in >= 9 && in_sizes[3] == 1) i = 4;   // scalar k materialized
    const float* W1a = (const float*)d_in[i + 0];
    const float* W1b = (const float*)d_in[i + 1];
    const float* b1  = (const float*)d_in[i + 2];
    const float* W2  = (const float*)d_in[i + 3];
    const float* b2  = (const float*)d_in[i + 4];
    float* out = (float*)d_out;

    const int scores_elems = NUMG * 1024;
    const int pairs_elems  = NUMG * 1024 * 2;
    int write_pairs = (out_size >= scores_elems + pairs_elems) ? 1 : 0;

    const int DSM = 49152;   // Ahi/Alo 16KB + Bhi/Blo 8KB each
    cudaFuncSetAttribute(gemm_mma_kernel,
                         cudaFuncAttributeMaxDynamicSharedMemorySize, DSM);

    gemm_mma_kernel<<<256, 256, DSM>>>(orig, ind0, ind1, W1a, W1b, b1);
    pairwise_kernel<<<512, 256>>>(W2, b2, out, write_pairs);
}

// round 12
// speedup vs baseline: 1.1288x; 1.1288x over previous
#include <cuda_runtime.h>
#include <cuda_bf16.h>
#include <cstdint>

// orig_fea [256, 300, 256] f32; ind0/ind1 [32,32,4] i32; W1a/W1b [256,256];
// b1[256]; W2[256,1]; b2[1]. L=128, pool=1200.
#define LN   128
#define DD   256
#define HH   256
#define NUMG 32
#define BAG  300

// Scratch: h0/h1 transposed: [side][n][h][a]  (8 MB)
__device__ float g_hT[2][NUMG][HH][LN];

// ============================ helpers ============================
__device__ __forceinline__ uint32_t smem_u32(const void* p) {
    uint32_t a;
    asm("{ .reg .u64 t; cvta.to.shared.u64 t, %1; cvt.u32.u64 %0, t; }"
        : "=r"(a) : "l"(p));
    return a;
}
// f32 pair -> bf16x2 (low half = x0); also return rounded values as f32
__device__ __forceinline__ uint32_t cvt_pair(float x0, float x1, float& h0f, float& h1f) {
    uint32_t r;
    asm("cvt.rn.bf16x2.f32 %0, %1, %2;" : "=r"(r) : "f"(x1), "f"(x0));
    h0f = __uint_as_float(r << 16);
    h1f = __uint_as_float(r & 0xFFFF0000u);
    return r;
}
__device__ __forceinline__ uint32_t cvt_pair_n(float x0, float x1) {
    uint32_t r;
    asm("cvt.rn.bf16x2.f32 %0, %1, %2;" : "=r"(r) : "f"(x1), "f"(x0));
    return r;
}
__device__ __forceinline__ void ldsm4(uint32_t* r, uint32_t addr) {
    asm volatile("ldmatrix.sync.aligned.m8n8.x4.shared.b16 {%0,%1,%2,%3}, [%4];"
        : "=r"(r[0]), "=r"(r[1]), "=r"(r[2]), "=r"(r[3]) : "r"(addr));
}
__device__ __forceinline__ void ldsm4t(uint32_t* r, uint32_t addr) {
    asm volatile("ldmatrix.sync.aligned.m8n8.x4.trans.shared.b16 {%0,%1,%2,%3}, [%4];"
        : "=r"(r[0]), "=r"(r[1]), "=r"(r[2]), "=r"(r[3]) : "r"(addr));
}
__device__ __forceinline__ void mma16816(float* d, const uint32_t* a,
                                         uint32_t b0, uint32_t b1) {
    asm volatile("mma.sync.aligned.m16n8k16.row.col.f32.bf16.bf16.f32 "
        "{%0,%1,%2,%3}, {%4,%5,%6,%7}, {%8,%9}, {%0,%1,%2,%3};"
        : "+f"(d[0]), "+f"(d[1]), "+f"(d[2]), "+f"(d[3])
        : "r"(a[0]), "r"(a[1]), "r"(a[2]), "r"(a[3]), "r"(b0), "r"(b1));
}
// XOR swizzle: rows of 128B, 16B atoms permuted by row%8 -> conflict-free LDSM
#define SWZ(row, kb) ((row) * 128 + ((kb) ^ (((row) & 7) << 4)))

// ---------------------------------------------------------------------------
// Kernel 1: mma.sync bf16 split-precision GEMM, register-prefetch pipelined:
// double smem buffers (96KB), prefetch chunk c+1 LDGs before computing chunk c,
// cvt+STS after compute, ONE barrier per chunk (was two).
// grid 256 = side(2) x n(32) x h-quad(4). block 256 = 8 warps (4m x 2n).
// ---------------------------------------------------------------------------
__global__ __launch_bounds__(256)
void gemm_mma_kernel(const float* __restrict__ orig,
                     const int*   __restrict__ ind0,
                     const int*   __restrict__ ind1,
                     const float* __restrict__ W1a,
                     const float* __restrict__ W1b,
                     const float* __restrict__ bias1)
{
    extern __shared__ char dsm[];
    __shared__ int rowoff[128];

    const int t = threadIdx.x, l = t & 31, w = t >> 5;
    const int b    = blockIdx.x;
    const int side = b >> 7;
    const int n    = (b >> 2) & 31;
    const int h0   = (b & 3) * 64;
    const int m0   = (w & 3) * 32;
    const int n0   = (w >> 2) * 32;
    const float* __restrict__ Wmat = side ? W1b : W1a;

    const uint32_t smb = smem_u32(dsm);
    // per-buffer layout: Ahi 0, Alo 16384, Bhi 32768, Blo 40960; stride 49152
    const int BUFS = 49152;

    if (t < 128) {
        const int* __restrict__ ind = side ? ind1 : ind0;
        int p = ind[n * LN + t] + BAG * (t & 3);
        rowoff[t] = ((n * 2 + side) * 1200 + p) * DD;
    }
    __syncthreads();

    const int arow  = t >> 1;
    const int halfk = t & 1;
    const int ro    = rowoff[arow];
    const int bkr   = t >> 2;
    const int bhq   = t & 3;

    float acc[2][4][4];
#pragma unroll
    for (int mt = 0; mt < 2; mt++)
#pragma unroll
        for (int nt = 0; nt < 4; nt++)
#pragma unroll
            for (int i = 0; i < 4; i++) acc[mt][nt][i] = 0.f;

    float4 av[8], wv[4];

    // convert + store staged registers into buffer `buf`
    auto stage_to_smem = [&](int buf) {
        char* base = dsm + buf * BUFS;
#pragma unroll
        for (int q2 = 0; q2 < 4; q2++) {
            float4 u = av[2 * q2], v = av[2 * q2 + 1];
            float r0, r1, r2, r3, r4, r5, r6, r7;
            uint32_t hp0 = cvt_pair(u.x, u.y, r0, r1);
            uint32_t hp1 = cvt_pair(u.z, u.w, r2, r3);
            uint32_t hp2 = cvt_pair(v.x, v.y, r4, r5);
            uint32_t hp3 = cvt_pair(v.z, v.w, r6, r7);
            uint32_t lp0 = cvt_pair_n(u.x - r0, u.y - r1);
            uint32_t lp1 = cvt_pair_n(u.z - r2, u.w - r3);
            uint32_t lp2 = cvt_pair_n(v.x - r4, v.y - r5);
            uint32_t lp3 = cvt_pair_n(v.z - r6, v.w - r7);
            int kb = halfk * 64 + q2 * 16;
            *(uint4*)(base + 0     + SWZ(arow, kb)) = make_uint4(hp0, hp1, hp2, hp3);
            *(uint4*)(base + 16384 + SWZ(arow, kb)) = make_uint4(lp0, lp1, lp2, lp3);
        }
        uint32_t hi[8], lo[8];
#pragma unroll
        for (int q2 = 0; q2 < 2; q2++) {
            float4 u = wv[2 * q2], v = wv[2 * q2 + 1];
            float r0, r1, r2, r3, r4, r5, r6, r7;
            hi[q2 * 4 + 0] = cvt_pair(u.x, u.y, r0, r1);
            hi[q2 * 4 + 1] = cvt_pair(u.z, u.w, r2, r3);
            hi[q2 * 4 + 2] = cvt_pair(v.x, v.y, r4, r5);
            hi[q2 * 4 + 3] = cvt_pair(v.z, v.w, r6, r7);
            lo[q2 * 4 + 0] = cvt_pair_n(u.x - r0, u.y - r1);
            lo[q2 * 4 + 1] = cvt_pair_n(u.z - r2, u.w - r3);
            lo[q2 * 4 + 2] = cvt_pair_n(v.x - r4, v.y - r5);
            lo[q2 * 4 + 3] = cvt_pair_n(v.z - r6, v.w - r7);
        }
        int kb = bhq * 32;
        *(uint4*)(base + 32768 + SWZ(bkr, kb))      = make_uint4(hi[0], hi[1], hi[2], hi[3]);
        *(uint4*)(base + 32768 + SWZ(bkr, kb + 16)) = make_uint4(hi[4], hi[5], hi[6], hi[7]);
        *(uint4*)(base + 40960 + SWZ(bkr, kb))      = make_uint4(lo[0], lo[1], lo[2], lo[3]);
        *(uint4*)(base + 40960 + SWZ(bkr, kb + 16)) = make_uint4(lo[4], lo[5], lo[6], lo[7]);
    };

    // prologue: load + stage chunk 0
    {
        const float4* ap = (const float4*)(orig + ro + 0 + halfk * 32);
#pragma unroll
        for (int q = 0; q < 8; q++) av[q] = ap[q];
        const float4* wp = (const float4*)&Wmat[(0 + bkr) * HH + h0 + bhq * 16];
#pragma unroll
        for (int q = 0; q < 4; q++) wv[q] = wp[q];
        stage_to_smem(0);
    }
    __syncthreads();

#pragma unroll 1
    for (int c = 0; c < 4; c++) {
        const int buf = c & 1;
        // prefetch next chunk's LDGs (overlap with compute below)
        if (c < 3) {
            const float4* ap = (const float4*)(orig + ro + (c + 1) * 64 + halfk * 32);
#pragma unroll
            for (int q = 0; q < 8; q++) av[q] = ap[q];
            const float4* wp = (const float4*)&Wmat[((c + 1) * 64 + bkr) * HH + h0 + bhq * 16];
#pragma unroll
            for (int q = 0; q < 4; q++) wv[q] = wp[q];
        }
        // compute chunk c from buf
        const uint32_t bb = smb + buf * BUFS;
#pragma unroll
        for (int ks = 0; ks < 4; ks++) {
            const int rA  = m0 + (l & 15);
            const int kbL = ks * 32 + ((l >> 4) << 4);
            uint32_t ahi[2][4], alo[2][4], bhi[2][4], blo[2][4];
            ldsm4(ahi[0], bb + 0     + SWZ(rA, kbL));
            ldsm4(ahi[1], bb + 0     + SWZ(rA + 16, kbL));
            ldsm4(alo[0], bb + 16384 + SWZ(rA, kbL));
            ldsm4(alo[1], bb + 16384 + SWZ(rA + 16, kbL));
            const int rK = ks * 16 + (l & 15);
            const int hb = ((l >> 4) << 4);
            ldsm4t(bhi[0], bb + 32768 + SWZ(rK, n0 * 2 + hb));
            ldsm4t(bhi[1], bb + 32768 + SWZ(rK, n0 * 2 + 32 + hb));
            ldsm4t(blo[0], bb + 40960 + SWZ(rK, n0 * 2 + hb));
            ldsm4t(blo[1], bb + 40960 + SWZ(rK, n0 * 2 + 32 + hb));
#pragma unroll
            for (int mt = 0; mt < 2; mt++)
#pragma unroll
                for (int g = 0; g < 2; g++)
#pragma unroll
                    for (int s = 0; s < 2; s++) {
                        int nt = g * 2 + s;
                        mma16816(acc[mt][nt], ahi[mt], bhi[g][2 * s], bhi[g][2 * s + 1]);
                        mma16816(acc[mt][nt], alo[mt], bhi[g][2 * s], bhi[g][2 * s + 1]);
                        mma16816(acc[mt][nt], ahi[mt], blo[g][2 * s], blo[g][2 * s + 1]);
                    }
        }
        // stage next chunk into the other buffer; fast warps write while slow
        // warps still read buf (different buffer -> safe); then one barrier.
        if (c < 3) {
            stage_to_smem(buf ^ 1);
            __syncthreads();
        }
    }

    const int g    = l >> 2;
    const int tid4 = l & 3;
#pragma unroll
    for (int mt = 0; mt < 2; mt++) {
        int ag = m0 + mt * 16 + g;
#pragma unroll
        for (int nt = 0; nt < 4; nt++) {
            int hg = h0 + n0 + nt * 8 + tid4 * 2;
            float bv0 = 0.f, bv1 = 0.f;
            if (side == 0) { bv0 = __ldg(&bias1[hg]); bv1 = __ldg(&bias1[hg + 1]); }
            g_hT[side][n][hg    ][ag    ] = acc[mt][nt][0] + bv0;
            g_hT[side][n][hg + 1][ag    ] = acc[mt][nt][1] + bv1;
            g_hT[side][n][hg    ][ag + 8] = acc[mt][nt][2] + bv0;
            g_hT[side][n][hg + 1][ag + 8] = acc[mt][nt][3] + bv1;
        }
    }
}

// ---------------------------------------------------------------------------
// Kernel 2: EXACT R10 winner (22.8us): smem-staged, relu via s+|s| (fma pipe),
// W2 pre-halved in smem.
// grid 512 = n(32) x a-tile(8, 16 a) x b-tile(2, 64 b); block 256.
// ---------------------------------------------------------------------------
__global__ __launch_bounds__(256)
void pairwise_kernel(const float* __restrict__ W2,
                     const float* __restrict__ b2,
                     float* __restrict__ out,
                     int write_pairs)
{
    const int bid = blockIdx.x;
    const int n   = bid >> 4;
    const int at  = (bid >> 1) & 7;
    const int bt  = bid & 1;
    const int a0  = at * 16;
    const int b0  = bt * 64;
    const int t   = threadIdx.x;
    const int tx  = t & 15;
    const int ty  = (t >> 4) & 3;
    const int th  = t >> 6;

    __shared__ float4 xs4[256][4];       // [h][a-quad]  16KB
    __shared__ float4 ys4[2][32][16];    // [buf][h][b-quad]  16KB
    __shared__ float  ws[256];           // 0.5 * W2      1KB

#pragma unroll
    for (int r = 0; r < 4; r++) {
        int id = t + 256 * r;
        int hh = id >> 2, q = id & 3;
        xs4[hh][q] = *(const float4*)&g_hT[0][n][hh][a0 + q * 4];
    }
#pragma unroll
    for (int r = 0; r < 2; r++) {
        int id = t + 256 * r;
        int hh = id >> 4, q = id & 15;
        ys4[0][hh][q] = *(const float4*)&g_hT[1][n][hh][b0 + q * 4];
    }
    ws[t] = 0.5f * W2[t];
    __syncthreads();

    float acc[4][4];
#pragma unroll
    for (int j = 0; j < 4; j++)
#pragma unroll
        for (int i = 0; i < 4; i++) acc[j][i] = 0.f;

    int buf = 0;
#pragma unroll 1
    for (int hc = 0; hc < 8; hc++) {
        float4 st[2];
        if (hc < 7) {
#pragma unroll
            for (int r = 0; r < 2; r++) {
                int id = t + 256 * r;
                int hh = id >> 4, q = id & 15;
                st[r] = *(const float4*)&g_hT[1][n][(hc + 1) * 32 + hh][b0 + q * 4];
            }
        }
#pragma unroll
        for (int u = 0; u < 8; u++) {
            int hh = th + u * 4;
            int hs = hc * 32 + hh;
            float  wv = ws[hs];                 // pre-halved
            float4 x4 = xs4[hs][ty];
            float4 y4 = ys4[buf][hh][tx];
            float xa[4] = {x4.x, x4.y, x4.z, x4.w};
            float yb[4] = {y4.x, y4.y, y4.z, y4.w};
#pragma unroll
            for (int j = 0; j < 4; j++)
#pragma unroll
                for (int i = 0; i < 4; i++) {
                    float s = xa[j] + yb[i];
                    float uu = s + fabsf(s);     // FADD with |.| modifier
                    acc[j][i] = fmaf(uu, wv, acc[j][i]);
                }
        }
        if (hc < 7) {
            int nb = buf ^ 1;
#pragma unroll
            for (int r = 0; r < 2; r++) {
                int id = t + 256 * r;
                int hh = id >> 4, q = id & 15;
                ys4[nb][hh][q] = st[r];
            }
            __syncthreads();
            buf = nb;
        }
    }

    // 4-way reduction in dead xs region (16KB)
    float* red = (float*)&xs4[0][0];
    const int p = ty * 16 + tx;   // 0..63
    __syncthreads();
    if (th > 0) {
        int base = ((th - 1) * 64 + p) * 16;
#pragma unroll
        for (int j = 0; j < 4; j++)
#pragma unroll
            for (int i = 0; i < 4; i++) {
                int idx = j * 4 + i;
                red[base + ((idx + p) & 15)] = acc[j][i];
            }
    }
    __syncthreads();
    if (th == 0) {
        float s = 0.f;
#pragma unroll
        for (int j = 0; j < 4; j++)
#pragma unroll
            for (int i = 0; i < 4; i++) s += acc[j][i];
#pragma unroll
        for (int g = 0; g < 3; g++) {
            int base = (g * 64 + p) * 16;
#pragma unroll
            for (int idx = 0; idx < 16; idx++)
                s += red[base + ((idx + p) & 15)];
        }
        s += 16.f * __ldg(b2);
        const int m = at * 4 + ty;
        const int lcol = bt * 16 + tx;
        out[n * 1024 + m * 32 + lcol] = s;
    }

    if (write_pairs && t < 128) {
        int id    = bid * 128 + t;   // 0..65535
        int pi    = id >> 1;
        int which = id & 1;
        int idx   = pi & 1023;
        int v = which ? (idx & 31) : (idx >> 5);
        out[NUMG * 1024 + id] = (float)v;
    }
}

extern "C" void kernel_launch(void* const* d_in, const int* in_sizes, int n_in,
                              void* d_out, int out_size)
{
    const float* orig = (const float*)d_in[0];
    const int*   ind0 = (const int*)d_in[1];
    const int*   ind1 = (const int*)d_in[2];
    int i = 3;
    if (n_in >= 9 && in_sizes[3] == 1) i = 4;   // scalar k materialized
    const float* W1a = (const float*)d_in[i + 0];
    const float* W1b = (const float*)d_in[i + 1];
    const float* b1  = (const float*)d_in[i + 2];
    const float* W2  = (const float*)d_in[i + 3];
    const float* b2  = (const float*)d_in[i + 4];
    float* out = (float*)d_out;

    const int scores_elems = NUMG * 1024;
    const int pairs_elems  = NUMG * 1024 * 2;
    int write_pairs = (out_size >= scores_elems + pairs_elems) ? 1 : 0;

    const int DSM = 2 * 49152;   // double-buffered tiles, 96KB
    cudaFuncSetAttribute(gemm_mma_kernel,
                         cudaFuncAttributeMaxDynamicSharedMemorySize, DSM);

    gemm_mma_kernel<<<256, 256, DSM>>>(orig, ind0, ind1, W1a, W1b, b1);
    pairwise_kernel<<<512, 256>>>(W2, b2, out, write_pairs);
}

// round 13
// speedup vs baseline: 1.1296x; 1.0007x over previous
#include <cuda_runtime.h>
#include <cuda_bf16.h>
#include <cstdint>

// orig_fea [256, 300, 256] f32; ind0/ind1 [32,32,4] i32; W1a/W1b [256,256];
// b1[256]; W2[256,1]; b2[1]. L=128, pool=1200.
#define LN   128
#define DD   256
#define HH   256
#define NUMG 32
#define BAG  300

// Scratch: h0/h1 transposed: [side][n][h][a]  (8 MB)
__device__ float g_hT[2][NUMG][HH][LN];

// ============================ helpers ============================
__device__ __forceinline__ uint32_t smem_u32(const void* p) {
    uint32_t a;
    asm("{ .reg .u64 t; cvta.to.shared.u64 t, %1; cvt.u32.u64 %0, t; }"
        : "=r"(a) : "l"(p));
    return a;
}
// f32 pair -> bf16x2 (low half = x0); also return rounded values as f32
__device__ __forceinline__ uint32_t cvt_pair(float x0, float x1, float& h0f, float& h1f) {
    uint32_t r;
    asm("cvt.rn.bf16x2.f32 %0, %1, %2;" : "=r"(r) : "f"(x1), "f"(x0));
    h0f = __uint_as_float(r << 16);
    h1f = __uint_as_float(r & 0xFFFF0000u);
    return r;
}
__device__ __forceinline__ uint32_t cvt_pair_n(float x0, float x1) {
    uint32_t r;
    asm("cvt.rn.bf16x2.f32 %0, %1, %2;" : "=r"(r) : "f"(x1), "f"(x0));
    return r;
}
__device__ __forceinline__ void ldsm4(uint32_t* r, uint32_t addr) {
    asm volatile("ldmatrix.sync.aligned.m8n8.x4.shared.b16 {%0,%1,%2,%3}, [%4];"
        : "=r"(r[0]), "=r"(r[1]), "=r"(r[2]), "=r"(r[3]) : "r"(addr));
}
__device__ __forceinline__ void ldsm4t(uint32_t* r, uint32_t addr) {
    asm volatile("ldmatrix.sync.aligned.m8n8.x4.trans.shared.b16 {%0,%1,%2,%3}, [%4];"
        : "=r"(r[0]), "=r"(r[1]), "=r"(r[2]), "=r"(r[3]) : "r"(addr));
}
__device__ __forceinline__ void mma16816(float* d, const uint32_t* a,
                                         uint32_t b0, uint32_t b1) {
    asm volatile("mma.sync.aligned.m16n8k16.row.col.f32.bf16.bf16.f32 "
        "{%0,%1,%2,%3}, {%4,%5,%6,%7}, {%8,%9}, {%0,%1,%2,%3};"
        : "+f"(d[0]), "+f"(d[1]), "+f"(d[2]), "+f"(d[3])
        : "r"(a[0]), "r"(a[1]), "r"(a[2]), "r"(a[3]), "r"(b0), "r"(b1));
}
// XOR swizzle: rows of 128B, 16B atoms permuted by row%8 -> conflict-free LDSM
#define SWZ(row, kb) ((row) * 128 + ((kb) ^ (((row) & 7) << 4)))

// ---------------------------------------------------------------------------
// Kernel 1: mma.sync bf16 split-precision GEMM, register-prefetch pipelined
// (UNCHANGED from R12 winner).
// ---------------------------------------------------------------------------
__global__ __launch_bounds__(256)
void gemm_mma_kernel(const float* __restrict__ orig,
                     const int*   __restrict__ ind0,
                     const int*   __restrict__ ind1,
                     const float* __restrict__ W1a,
                     const float* __restrict__ W1b,
                     const float* __restrict__ bias1)
{
    extern __shared__ char dsm[];
    __shared__ int rowoff[128];

    const int t = threadIdx.x, l = t & 31, w = t >> 5;
    const int b    = blockIdx.x;
    const int side = b >> 7;
    const int n    = (b >> 2) & 31;
    const int h0   = (b & 3) * 64;
    const int m0   = (w & 3) * 32;
    const int n0   = (w >> 2) * 32;
    const float* __restrict__ Wmat = side ? W1b : W1a;

    const uint32_t smb = smem_u32(dsm);
    const int BUFS = 49152;

    if (t < 128) {
        const int* __restrict__ ind = side ? ind1 : ind0;
        int p = ind[n * LN + t] + BAG * (t & 3);
        rowoff[t] = ((n * 2 + side) * 1200 + p) * DD;
    }
    __syncthreads();

    const int arow  = t >> 1;
    const int halfk = t & 1;
    const int ro    = rowoff[arow];
    const int bkr   = t >> 2;
    const int bhq   = t & 3;

    float acc[2][4][4];
#pragma unroll
    for (int mt = 0; mt < 2; mt++)
#pragma unroll
        for (int nt = 0; nt < 4; nt++)
#pragma unroll
            for (int i = 0; i < 4; i++) acc[mt][nt][i] = 0.f;

    float4 av[8], wv[4];

    auto stage_to_smem = [&](int buf) {
        char* base = dsm + buf * BUFS;
#pragma unroll
        for (int q2 = 0; q2 < 4; q2++) {
            float4 u = av[2 * q2], v = av[2 * q2 + 1];
            float r0, r1, r2, r3, r4, r5, r6, r7;
            uint32_t hp0 = cvt_pair(u.x, u.y, r0, r1);
            uint32_t hp1 = cvt_pair(u.z, u.w, r2, r3);
            uint32_t hp2 = cvt_pair(v.x, v.y, r4, r5);
            uint32_t hp3 = cvt_pair(v.z, v.w, r6, r7);
            uint32_t lp0 = cvt_pair_n(u.x - r0, u.y - r1);
            uint32_t lp1 = cvt_pair_n(u.z - r2, u.w - r3);
            uint32_t lp2 = cvt_pair_n(v.x - r4, v.y - r5);
            uint32_t lp3 = cvt_pair_n(v.z - r6, v.w - r7);
            int kb = halfk * 64 + q2 * 16;
            *(uint4*)(base + 0     + SWZ(arow, kb)) = make_uint4(hp0, hp1, hp2, hp3);
            *(uint4*)(base + 16384 + SWZ(arow, kb)) = make_uint4(lp0, lp1, lp2, lp3);
        }
        uint32_t hi[8], lo[8];
#pragma unroll
        for (int q2 = 0; q2 < 2; q2++) {
            float4 u = wv[2 * q2], v = wv[2 * q2 + 1];
            float r0, r1, r2, r3, r4, r5, r6, r7;
            hi[q2 * 4 + 0] = cvt_pair(u.x, u.y, r0, r1);
            hi[q2 * 4 + 1] = cvt_pair(u.z, u.w, r2, r3);
            hi[q2 * 4 + 2] = cvt_pair(v.x, v.y, r4, r5);
            hi[q2 * 4 + 3] = cvt_pair(v.z, v.w, r6, r7);
            lo[q2 * 4 + 0] = cvt_pair_n(u.x - r0, u.y - r1);
            lo[q2 * 4 + 1] = cvt_pair_n(u.z - r2, u.w - r3);
            lo[q2 * 4 + 2] = cvt_pair_n(v.x - r4, v.y - r5);
            lo[q2 * 4 + 3] = cvt_pair_n(v.z - r6, v.w - r7);
        }
        int kb = bhq * 32;
        *(uint4*)(base + 32768 + SWZ(bkr, kb))      = make_uint4(hi[0], hi[1], hi[2], hi[3]);
        *(uint4*)(base + 32768 + SWZ(bkr, kb + 16)) = make_uint4(hi[4], hi[5], hi[6], hi[7]);
        *(uint4*)(base + 40960 + SWZ(bkr, kb))      = make_uint4(lo[0], lo[1], lo[2], lo[3]);
        *(uint4*)(base + 40960 + SWZ(bkr, kb + 16)) = make_uint4(lo[4], lo[5], lo[6], lo[7]);
    };

    {
        const float4* ap = (const float4*)(orig + ro + 0 + halfk * 32);
#pragma unroll
        for (int q = 0; q < 8; q++) av[q] = ap[q];
        const float4* wp = (const float4*)&Wmat[(0 + bkr) * HH + h0 + bhq * 16];
#pragma unroll
        for (int q = 0; q < 4; q++) wv[q] = wp[q];
        stage_to_smem(0);
    }
    __syncthreads();

#pragma unroll 1
    for (int c = 0; c < 4; c++) {
        const int buf = c & 1;
        if (c < 3) {
            const float4* ap = (const float4*)(orig + ro + (c + 1) * 64 + halfk * 32);
#pragma unroll
            for (int q = 0; q < 8; q++) av[q] = ap[q];
            const float4* wp = (const float4*)&Wmat[((c + 1) * 64 + bkr) * HH + h0 + bhq * 16];
#pragma unroll
            for (int q = 0; q < 4; q++) wv[q] = wp[q];
        }
        const uint32_t bb = smb + buf * BUFS;
#pragma unroll
        for (int ks = 0; ks < 4; ks++) {
            const int rA  = m0 + (l & 15);
            const int kbL = ks * 32 + ((l >> 4) << 4);
            uint32_t ahi[2][4], alo[2][4], bhi[2][4], blo[2][4];
            ldsm4(ahi[0], bb + 0     + SWZ(rA, kbL));
            ldsm4(ahi[1], bb + 0     + SWZ(rA + 16, kbL));
            ldsm4(alo[0], bb + 16384 + SWZ(rA, kbL));
            ldsm4(alo[1], bb + 16384 + SWZ(rA + 16, kbL));
            const int rK = ks * 16 + (l & 15);
            const int hb = ((l >> 4) << 4);
            ldsm4t(bhi[0], bb + 32768 + SWZ(rK, n0 * 2 + hb));
            ldsm4t(bhi[1], bb + 32768 + SWZ(rK, n0 * 2 + 32 + hb));
            ldsm4t(blo[0], bb + 40960 + SWZ(rK, n0 * 2 + hb));
            ldsm4t(blo[1], bb + 40960 + SWZ(rK, n0 * 2 + 32 + hb));
#pragma unroll
            for (int mt = 0; mt < 2; mt++)
#pragma unroll
                for (int g = 0; g < 2; g++)
#pragma unroll
                    for (int s = 0; s < 2; s++) {
                        int nt = g * 2 + s;
                        mma16816(acc[mt][nt], ahi[mt], bhi[g][2 * s], bhi[g][2 * s + 1]);
                        mma16816(acc[mt][nt], alo[mt], bhi[g][2 * s], bhi[g][2 * s + 1]);
                        mma16816(acc[mt][nt], ahi[mt], blo[g][2 * s], blo[g][2 * s + 1]);
                    }
        }
        if (c < 3) {
            stage_to_smem(buf ^ 1);
            __syncthreads();
        }
    }

    const int g    = l >> 2;
    const int tid4 = l & 3;
#pragma unroll
    for (int mt = 0; mt < 2; mt++) {
        int ag = m0 + mt * 16 + g;
#pragma unroll
        for (int nt = 0; nt < 4; nt++) {
            int hg = h0 + n0 + nt * 8 + tid4 * 2;
            float bv0 = 0.f, bv1 = 0.f;
            if (side == 0) { bv0 = __ldg(&bias1[hg]); bv1 = __ldg(&bias1[hg + 1]); }
            g_hT[side][n][hg    ][ag    ] = acc[mt][nt][0] + bv0;
            g_hT[side][n][hg + 1][ag    ] = acc[mt][nt][1] + bv1;
            g_hT[side][n][hg    ][ag + 8] = acc[mt][nt][2] + bv0;
            g_hT[side][n][hg + 1][ag + 8] = acc[mt][nt][3] + bv1;
        }
    }
}

// ---------------------------------------------------------------------------
// Kernel 2 (REWORKED): warp-per-h-stripe, 4a x 8b per-thread tiles.
// Warp w handles h = w (mod 8); per u-iter: 4 LDS feed 96 payload fma-pipe ops
// (relu via bit-exact s + |s| with pre-halved W2). Constant-stride h advance
// kills per-iter IMADs. 8-way cross-warp reduction in a 2KB red array.
// grid 512 = n(32) x a-tile(8, 16 a) x b-tile(2, 64 b); block 256.
//   lane: tx = l&7 (8b each), ty = l>>3 (4a each); warp w = h stripe.
// ---------------------------------------------------------------------------
__global__ __launch_bounds__(256)
void pairwise_kernel(const float* __restrict__ W2,
                     const float* __restrict__ b2,
                     float* __restrict__ out,
                     int write_pairs)
{
    const int bid = blockIdx.x;
    const int n   = bid >> 4;
    const int at  = (bid >> 1) & 7;
    const int bt  = bid & 1;
    const int a0  = at * 16;
    const int b0  = bt * 64;
    const int t   = threadIdx.x;
    const int l   = t & 31;
    const int w   = t >> 5;       // 0..7, h stripe
    const int tx  = l & 7;        // 8 b-cols each
    const int ty  = l >> 3;       // 0..3, 4 a-rows each
    const int w4  = w * 4;

    __shared__ float4 xs4[256][4];       // [h][a-quad]      16KB
    __shared__ float4 ys4[2][32][16];    // [buf][h][b-quad] 16KB
    __shared__ float  ws[256];           // 0.5 * W2          1KB
    __shared__ float  red[8][64];        // cross-warp        2KB

#pragma unroll
    for (int r = 0; r < 4; r++) {
        int id = t + 256 * r;
        int hh = id >> 2, q = id & 3;
        xs4[hh][q] = *(const float4*)&g_hT[0][n][hh][a0 + q * 4];
    }
#pragma unroll
    for (int r = 0; r < 2; r++) {
        int id = t + 256 * r;
        int hh = id >> 4, q = id & 15;
        ys4[0][hh][q] = *(const float4*)&g_hT[1][n][hh][b0 + q * 4];
    }
    ws[t] = 0.5f * W2[t];
    __syncthreads();

    float acc[4][8];
#pragma unroll
    for (int j = 0; j < 4; j++)
#pragma unroll
        for (int i = 0; i < 8; i++) acc[j][i] = 0.f;

    int buf = 0;
#pragma unroll 1
    for (int hc = 0; hc < 8; hc++) {
        float4 st[2];
        if (hc < 7) {
#pragma unroll
            for (int r = 0; r < 2; r++) {
                int id = t + 256 * r;
                int hh = id >> 4, q = id & 15;
                st[r] = *(const float4*)&g_hT[1][n][(hc + 1) * 32 + hh][b0 + q * 4];
            }
        }
#pragma unroll
        for (int u = 0; u < 4; u++) {
            const int hh = w4 + u;            // warp-contiguous 4 rows per chunk
            const int hs = hc * 32 + hh;
            float  wv = ws[hs];               // warp-uniform broadcast
            float4 x4 = xs4[hs][ty];
            float4 ya = ys4[buf][hh][tx * 2];
            float4 yb = ys4[buf][hh][tx * 2 + 1];
            float xa[4] = {x4.x, x4.y, x4.z, x4.w};
            float yv[8] = {ya.x, ya.y, ya.z, ya.w, yb.x, yb.y, yb.z, yb.w};
#pragma unroll
            for (int j = 0; j < 4; j++)
#pragma unroll
                for (int i = 0; i < 8; i++) {
                    float s  = xa[j] + yv[i];
                    float uu = s + fabsf(s);   // 2*relu(s), exact
                    acc[j][i] = fmaf(uu, wv, acc[j][i]);
                }
        }
        if (hc < 7) {
            int nb = buf ^ 1;
#pragma unroll
            for (int r = 0; r < 2; r++) {
                int id = t + 256 * r;
                int hh = id >> 4, q = id & 15;
                ys4[nb][hh][q] = st[r];
            }
            __syncthreads();
            buf = nb;
        }
    }

    // per-thread: two 4x4 patch sums (b-cols tx*8..+3 and +4..+7)
    float s0 = 0.f, s1 = 0.f;
#pragma unroll
    for (int j = 0; j < 4; j++) {
        s0 += acc[j][0] + acc[j][1] + acc[j][2] + acc[j][3];
        s1 += acc[j][4] + acc[j][5] + acc[j][6] + acc[j][7];
    }
    red[w][(ty * 8 + tx) * 2    ] = s0;
    red[w][(ty * 8 + tx) * 2 + 1] = s1;
    __syncthreads();

    if (t < 64) {
        const int m  = t >> 4;        // 0..3
        const int li = t & 15;        // 0..15
        const int slot = (m * 8 + (li >> 1)) * 2 + (li & 1);
        float s = 0.f;
#pragma unroll
        for (int g = 0; g < 8; g++) s += red[g][slot];
        s += 16.f * __ldg(b2);
        out[n * 1024 + (at * 4 + m) * 32 + bt * 16 + li] = s;
    }

    if (write_pairs && t < 128) {
        int id    = bid * 128 + t;   // 0..65535
        int pi    = id >> 1;
        int which = id & 1;
        int idx   = pi & 1023;
        int v = which ? (idx & 31) : (idx >> 5);
        out[NUMG * 1024 + id] = (float)v;
    }
}

extern "C" void kernel_launch(void* const* d_in, const int* in_sizes, int n_in,
                              void* d_out, int out_size)
{
    const float* orig = (const float*)d_in[0];
    const int*   ind0 = (const int*)d_in[1];
    const int*   ind1 = (const int*)d_in[2];
    int i = 3;
    if (n_in >= 9 && in_sizes[3] == 1) i = 4;   // scalar k materialized
    const float* W1a = (const float*)d_in[i + 0];
    const float* W1b = (const float*)d_in[i + 1];
    const float* b1  = (const float*)d_in[i + 2];
    const float* W2  = (const float*)d_in[i + 3];
    const float* b2  = (const float*)d_in[i + 4];
    float* out = (float*)d_out;

    const int scores_elems = NUMG * 1024;
    const int pairs_elems  = NUMG * 1024 * 2;
    int write_pairs = (out_size >= scores_elems + pairs_elems) ? 1 : 0;

    const int DSM = 2 * 49152;   // double-buffered tiles, 96KB
    cudaFuncSetAttribute(gemm_mma_kernel,
                         cudaFuncAttributeMaxDynamicSharedMemorySize, DSM);

    gemm_mma_kernel<<<256, 256, DSM>>>(orig, ind0, ind1, W1a, W1b, b1);
    pairwise_kernel<<<512, 256>>>(W2, b2, out, write_pairs);
}

// round 14
// speedup vs baseline: 1.1728x; 1.0382x over previous
#include <cuda_runtime.h>
#include <cuda_bf16.h>
#include <cstdint>

// orig_fea [256, 300, 256] f32; ind0/ind1 [32,32,4] i32; W1a/W1b [256,256];
// b1[256]; W2[256,1]; b2[1]. L=128, pool=1200.
#define LN   128
#define DD   256
#define HH   256
#define NUMG 32
#define BAG  300

// Scratch: h0/h1 transposed: [side][n][h][a]  (8 MB)
__device__ float g_hT[2][NUMG][HH][LN];

// ============================ helpers ============================
__device__ __forceinline__ uint32_t smem_u32(const void* p) {
    uint32_t a;
    asm("{ .reg .u64 t; cvta.to.shared.u64 t, %1; cvt.u32.u64 %0, t; }"
        : "=r"(a) : "l"(p));
    return a;
}
// f32 pair -> bf16x2 (low half = x0); also return rounded values as f32
__device__ __forceinline__ uint32_t cvt_pair(float x0, float x1, float& h0f, float& h1f) {
    uint32_t r;
    asm("cvt.rn.bf16x2.f32 %0, %1, %2;" : "=r"(r) : "f"(x1), "f"(x0));
    h0f = __uint_as_float(r << 16);
    h1f = __uint_as_float(r & 0xFFFF0000u);
    return r;
}
__device__ __forceinline__ uint32_t cvt_pair_n(float x0, float x1) {
    uint32_t r;
    asm("cvt.rn.bf16x2.f32 %0, %1, %2;" : "=r"(r) : "f"(x1), "f"(x0));
    return r;
}
__device__ __forceinline__ void ldsm4(uint32_t* r, uint32_t addr) {
    asm volatile("ldmatrix.sync.aligned.m8n8.x4.shared.b16 {%0,%1,%2,%3}, [%4];"
        : "=r"(r[0]), "=r"(r[1]), "=r"(r[2]), "=r"(r[3]) : "r"(addr));
}
__device__ __forceinline__ void ldsm4t(uint32_t* r, uint32_t addr) {
    asm volatile("ldmatrix.sync.aligned.m8n8.x4.trans.shared.b16 {%0,%1,%2,%3}, [%4];"
        : "=r"(r[0]), "=r"(r[1]), "=r"(r[2]), "=r"(r[3]) : "r"(addr));
}
__device__ __forceinline__ void mma16816(float* d, const uint32_t* a,
                                         uint32_t b0, uint32_t b1) {
    asm volatile("mma.sync.aligned.m16n8k16.row.col.f32.bf16.bf16.f32 "
        "{%0,%1,%2,%3}, {%4,%5,%6,%7}, {%8,%9}, {%0,%1,%2,%3};"
        : "+f"(d[0]), "+f"(d[1]), "+f"(d[2]), "+f"(d[3])
        : "r"(a[0]), "r"(a[1]), "r"(a[2]), "r"(a[3]), "r"(b0), "r"(b1));
}
// XOR swizzle: rows of 128B, 16B atoms permuted by row%8 -> conflict-free LDSM
#define SWZ(row, kb) ((row) * 128 + ((kb) ^ (((row) & 7) << 4)))

// ---------------------------------------------------------------------------
// Kernel 1: mma.sync bf16 split-precision GEMM, register-prefetch pipelined
// (UNCHANGED from R12/R13).
// ---------------------------------------------------------------------------
__global__ __launch_bounds__(256)
void gemm_mma_kernel(const float* __restrict__ orig,
                     const int*   __restrict__ ind0,
                     const int*   __restrict__ ind1,
                     const float* __restrict__ W1a,
                     const float* __restrict__ W1b,
                     const float* __restrict__ bias1)
{
    extern __shared__ char dsm[];
    __shared__ int rowoff[128];

    const int t = threadIdx.x, l = t & 31, w = t >> 5;
    const int b    = blockIdx.x;
    const int side = b >> 7;
    const int n    = (b >> 2) & 31;
    const int h0   = (b & 3) * 64;
    const int m0   = (w & 3) * 32;
    const int n0   = (w >> 2) * 32;
    const float* __restrict__ Wmat = side ? W1b : W1a;

    const uint32_t smb = smem_u32(dsm);
    const int BUFS = 49152;

    if (t < 128) {
        const int* __restrict__ ind = side ? ind1 : ind0;
        int p = ind[n * LN + t] + BAG * (t & 3);
        rowoff[t] = ((n * 2 + side) * 1200 + p) * DD;
    }
    __syncthreads();

    const int arow  = t >> 1;
    const int halfk = t & 1;
    const int ro    = rowoff[arow];
    const int bkr   = t >> 2;
    const int bhq   = t & 3;

    float acc[2][4][4];
#pragma unroll
    for (int mt = 0; mt < 2; mt++)
#pragma unroll
        for (int nt = 0; nt < 4; nt++)
#pragma unroll
            for (int i = 0; i < 4; i++) acc[mt][nt][i] = 0.f;

    float4 av[8], wv[4];

    auto stage_to_smem = [&](int buf) {
        char* base = dsm + buf * BUFS;
#pragma unroll
        for (int q2 = 0; q2 < 4; q2++) {
            float4 u = av[2 * q2], v = av[2 * q2 + 1];
            float r0, r1, r2, r3, r4, r5, r6, r7;
            uint32_t hp0 = cvt_pair(u.x, u.y, r0, r1);
            uint32_t hp1 = cvt_pair(u.z, u.w, r2, r3);
            uint32_t hp2 = cvt_pair(v.x, v.y, r4, r5);
            uint32_t hp3 = cvt_pair(v.z, v.w, r6, r7);
            uint32_t lp0 = cvt_pair_n(u.x - r0, u.y - r1);
            uint32_t lp1 = cvt_pair_n(u.z - r2, u.w - r3);
            uint32_t lp2 = cvt_pair_n(v.x - r4, v.y - r5);
            uint32_t lp3 = cvt_pair_n(v.z - r6, v.w - r7);
            int kb = halfk * 64 + q2 * 16;
            *(uint4*)(base + 0     + SWZ(arow, kb)) = make_uint4(hp0, hp1, hp2, hp3);
            *(uint4*)(base + 16384 + SWZ(arow, kb)) = make_uint4(lp0, lp1, lp2, lp3);
        }
        uint32_t hi[8], lo[8];
#pragma unroll
        for (int q2 = 0; q2 < 2; q2++) {
            float4 u = wv[2 * q2], v = wv[2 * q2 + 1];
            float r0, r1, r2, r3, r4, r5, r6, r7;
            hi[q2 * 4 + 0] = cvt_pair(u.x, u.y, r0, r1);
            hi[q2 * 4 + 1] = cvt_pair(u.z, u.w, r2, r3);
            hi[q2 * 4 + 2] = cvt_pair(v.x, v.y, r4, r5);
            hi[q2 * 4 + 3] = cvt_pair(v.z, v.w, r6, r7);
            lo[q2 * 4 + 0] = cvt_pair_n(u.x - r0, u.y - r1);
            lo[q2 * 4 + 1] = cvt_pair_n(u.z - r2, u.w - r3);
            lo[q2 * 4 + 2] = cvt_pair_n(v.x - r4, v.y - r5);
            lo[q2 * 4 + 3] = cvt_pair_n(v.z - r6, v.w - r7);
        }
        int kb = bhq * 32;
        *(uint4*)(base + 32768 + SWZ(bkr, kb))      = make_uint4(hi[0], hi[1], hi[2], hi[3]);
        *(uint4*)(base + 32768 + SWZ(bkr, kb + 16)) = make_uint4(hi[4], hi[5], hi[6], hi[7]);
        *(uint4*)(base + 40960 + SWZ(bkr, kb))      = make_uint4(lo[0], lo[1], lo[2], lo[3]);
        *(uint4*)(base + 40960 + SWZ(bkr, kb + 16)) = make_uint4(lo[4], lo[5], lo[6], lo[7]);
    };

    {
        const float4* ap = (const float4*)(orig + ro + 0 + halfk * 32);
#pragma unroll
        for (int q = 0; q < 8; q++) av[q] = ap[q];
        const float4* wp = (const float4*)&Wmat[(0 + bkr) * HH + h0 + bhq * 16];
#pragma unroll
        for (int q = 0; q < 4; q++) wv[q] = wp[q];
        stage_to_smem(0);
    }
    __syncthreads();

#pragma unroll 1
    for (int c = 0; c < 4; c++) {
        const int buf = c & 1;
        if (c < 3) {
            const float4* ap = (const float4*)(orig + ro + (c + 1) * 64 + halfk * 32);
#pragma unroll
            for (int q = 0; q < 8; q++) av[q] = ap[q];
            const float4* wp = (const float4*)&Wmat[((c + 1) * 64 + bkr) * HH + h0 + bhq * 16];
#pragma unroll
            for (int q = 0; q < 4; q++) wv[q] = wp[q];
        }
        const uint32_t bb = smb + buf * BUFS;
#pragma unroll
        for (int ks = 0; ks < 4; ks++) {
            const int rA  = m0 + (l & 15);
            const int kbL = ks * 32 + ((l >> 4) << 4);
            uint32_t ahi[2][4], alo[2][4], bhi[2][4], blo[2][4];
            ldsm4(ahi[0], bb + 0     + SWZ(rA, kbL));
            ldsm4(ahi[1], bb + 0     + SWZ(rA + 16, kbL));
            ldsm4(alo[0], bb + 16384 + SWZ(rA, kbL));
            ldsm4(alo[1], bb + 16384 + SWZ(rA + 16, kbL));
            const int rK = ks * 16 + (l & 15);
            const int hb = ((l >> 4) << 4);
            ldsm4t(bhi[0], bb + 32768 + SWZ(rK, n0 * 2 + hb));
            ldsm4t(bhi[1], bb + 32768 + SWZ(rK, n0 * 2 + 32 + hb));
            ldsm4t(blo[0], bb + 40960 + SWZ(rK, n0 * 2 + hb));
            ldsm4t(blo[1], bb + 40960 + SWZ(rK, n0 * 2 + 32 + hb));
#pragma unroll
            for (int mt = 0; mt < 2; mt++)
#pragma unroll
                for (int g = 0; g < 2; g++)
#pragma unroll
                    for (int s = 0; s < 2; s++) {
                        int nt = g * 2 + s;
                        mma16816(acc[mt][nt], ahi[mt], bhi[g][2 * s], bhi[g][2 * s + 1]);
                        mma16816(acc[mt][nt], alo[mt], bhi[g][2 * s], bhi[g][2 * s + 1]);
                        mma16816(acc[mt][nt], ahi[mt], blo[g][2 * s], blo[g][2 * s + 1]);
                    }
        }
        if (c < 3) {
            stage_to_smem(buf ^ 1);
            __syncthreads();
        }
    }

    const int g    = l >> 2;
    const int tid4 = l & 3;
#pragma unroll
    for (int mt = 0; mt < 2; mt++) {
        int ag = m0 + mt * 16 + g;
#pragma unroll
        for (int nt = 0; nt < 4; nt++) {
            int hg = h0 + n0 + nt * 8 + tid4 * 2;
            float bv0 = 0.f, bv1 = 0.f;
            if (side == 0) { bv0 = __ldg(&bias1[hg]); bv1 = __ldg(&bias1[hg + 1]); }
            g_hT[side][n][hg    ][ag    ] = acc[mt][nt][0] + bv0;
            g_hT[side][n][hg + 1][ag    ] = acc[mt][nt][1] + bv1;
            g_hT[side][n][hg    ][ag + 8] = acc[mt][nt][2] + bv0;
            g_hT[side][n][hg + 1][ag + 8] = acc[mt][nt][3] + bv1;
        }
    }
}

// ---------------------------------------------------------------------------
// Kernel 2: separable split:  relu(s)*w = s*(w/2) + |s|*(w/2).
// The s*(w/2) part is separable (X'_a + Y'_b, precomputed dots vs W2/2);
// the pairwise loop only accumulates |s|*(w/2): 2 fma-pipe ops per element
// (FADD; FFMA with |s|), dropping the fma-pipe floor from 23.6us to 15.7us.
// Structure otherwise identical to R13 (warp-per-h-stripe, 4a x 8b tiles).
// grid 512 = n(32) x a-tile(8, 16 a) x b-tile(2, 64 b); block 256.
// ---------------------------------------------------------------------------
__global__ __launch_bounds__(256)
void pairwise_kernel(const float* __restrict__ W2,
                     const float* __restrict__ b2,
                     float* __restrict__ out,
                     int write_pairs)
{
    const int bid = blockIdx.x;
    const int n   = bid >> 4;
    const int at  = (bid >> 1) & 7;
    const int bt  = bid & 1;
    const int a0  = at * 16;
    const int b0  = bt * 64;
    const int t   = threadIdx.x;
    const int l   = t & 31;
    const int w   = t >> 5;       // 0..7, h stripe
    const int tx  = l & 7;        // 8 b-cols each
    const int ty  = l >> 3;       // 0..3, 4 a-rows each
    const int w4  = w * 4;

    __shared__ float4 xs4[256][4];       // [h][a-quad]      16KB
    __shared__ float4 ys4[2][32][16];    // [buf][h][b-quad] 16KB
    __shared__ float  ws[256];           // 0.5 * W2          1KB
    __shared__ float  red[8][64];        // cross-warp        2KB
    __shared__ float  syq[4][64];        // Y' quarter sums   1KB
    __shared__ float  sxq[4][16];        // X' quarter sums  .25KB

#pragma unroll
    for (int r = 0; r < 4; r++) {
        int id = t + 256 * r;
        int hh = id >> 2, q = id & 3;
        xs4[hh][q] = *(const float4*)&g_hT[0][n][hh][a0 + q * 4];
    }
#pragma unroll
    for (int r = 0; r < 2; r++) {
        int id = t + 256 * r;
        int hh = id >> 4, q = id & 15;
        ys4[0][hh][q] = *(const float4*)&g_hT[1][n][hh][b0 + q * 4];
    }
    ws[t] = 0.5f * W2[t];
    __syncthreads();

    // ---- separable precompute: Y'_b = sum_h y*ws, X'_a = sum_h x*ws ----
    {   // all 256 threads: one (b, h-quarter) each; coalesced LDG from L2
        const int bb = t & 63, qt = t >> 6;
        const float* yp = &g_hT[1][n][qt * 64][b0 + bb];
        float p0 = 0.f, p1 = 0.f, p2 = 0.f, p3 = 0.f;
        const float* wq = &ws[qt * 64];
#pragma unroll
        for (int i = 0; i < 64; i += 4) {
            p0 = fmaf(yp[(i + 0) * LN], wq[i + 0], p0);
            p1 = fmaf(yp[(i + 1) * LN], wq[i + 1], p1);
            p2 = fmaf(yp[(i + 2) * LN], wq[i + 2], p2);
            p3 = fmaf(yp[(i + 3) * LN], wq[i + 3], p3);
        }
        syq[qt][bb] = (p0 + p1) + (p2 + p3);
    }
    if (t < 64) {   // one (a, h-quarter) each; from staged xs4
        const int aa = t & 15, qt = t >> 4;
        float p0 = 0.f, p1 = 0.f;
#pragma unroll
        for (int i = 0; i < 64; i += 2) {
            int h = qt * 64 + i;
            p0 = fmaf(((const float*)&xs4[h    ][0])[aa], ws[h    ], p0);
            p1 = fmaf(((const float*)&xs4[h + 1][0])[aa], ws[h + 1], p1);
        }
        sxq[qt][aa] = p0 + p1;
    }

    float acc[4][8];
#pragma unroll
    for (int j = 0; j < 4; j++)
#pragma unroll
        for (int i = 0; i < 8; i++) acc[j][i] = 0.f;

    int buf = 0;
#pragma unroll 1
    for (int hc = 0; hc < 8; hc++) {
        float4 st[2];
        if (hc < 7) {
#pragma unroll
            for (int r = 0; r < 2; r++) {
                int id = t + 256 * r;
                int hh = id >> 4, q = id & 15;
                st[r] = *(const float4*)&g_hT[1][n][(hc + 1) * 32 + hh][b0 + q * 4];
            }
        }
#pragma unroll
        for (int u = 0; u < 4; u++) {
            const int hh = w4 + u;
            const int hs = hc * 32 + hh;
            float  wv = ws[hs];
            float4 x4 = xs4[hs][ty];
            float4 ya = ys4[buf][hh][tx * 2];
            float4 yb = ys4[buf][hh][tx * 2 + 1];
            float xa[4] = {x4.x, x4.y, x4.z, x4.w};
            float yv[8] = {ya.x, ya.y, ya.z, ya.w, yb.x, yb.y, yb.z, yb.w};
#pragma unroll
            for (int j = 0; j < 4; j++)
#pragma unroll
                for (int i = 0; i < 8; i++) {
                    float s = xa[j] + yv[i];
                    acc[j][i] = fmaf(fabsf(s), wv, acc[j][i]);  // |s|*(w/2)
                }
        }
        if (hc < 7) {
            int nb = buf ^ 1;
#pragma unroll
            for (int r = 0; r < 2; r++) {
                int id = t + 256 * r;
                int hh = id >> 4, q = id & 15;
                ys4[nb][hh][q] = st[r];
            }
            __syncthreads();
            buf = nb;
        }
    }

    // per-thread: two 4x4 patch sums of the abs part
    float s0 = 0.f, s1 = 0.f;
#pragma unroll
    for (int j = 0; j < 4; j++) {
        s0 += acc[j][0] + acc[j][1] + acc[j][2] + acc[j][3];
        s1 += acc[j][4] + acc[j][5] + acc[j][6] + acc[j][7];
    }
    red[w][(ty * 8 + tx) * 2    ] = s0;
    red[w][(ty * 8 + tx) * 2 + 1] = s1;
    __syncthreads();

    if (t < 64) {
        const int m  = t >> 4;        // 0..3
        const int li = t & 15;        // 0..15
        const int slot = (m * 8 + (li >> 1)) * 2 + (li & 1);
        float s = 0.f;
#pragma unroll
        for (int g = 0; g < 8; g++) s += red[g][slot];
        // separable part: patch sum = 4*(sum_a X'_a + sum_b Y'_b)
        float sep = 0.f;
#pragma unroll
        for (int qt = 0; qt < 4; qt++)
#pragma unroll
            for (int p = 0; p < 4; p++)
                sep += sxq[qt][m * 4 + p] + syq[qt][li * 4 + p];
        s += 4.f * sep;
        s += 16.f * __ldg(b2);
        out[n * 1024 + (at * 4 + m) * 32 + bt * 16 + li] = s;
    }

    if (write_pairs && t < 128) {
        int id    = bid * 128 + t;   // 0..65535
        int pi    = id >> 1;
        int which = id & 1;
        int idx   = pi & 1023;
        int v = which ? (idx & 31) : (idx >> 5);
        out[NUMG * 1024 + id] = (float)v;
    }
}

extern "C" void kernel_launch(void* const* d_in, const int* in_sizes, int n_in,
                              void* d_out, int out_size)
{
    const float* orig = (const float*)d_in[0];
    const int*   ind0 = (const int*)d_in[1];
    const int*   ind1 = (const int*)d_in[2];
    int i = 3;
    if (n_in >= 9 && in_sizes[3] == 1) i = 4;   // scalar k materialized
    const float* W1a = (const float*)d_in[i + 0];
    const float* W1b = (const float*)d_in[i + 1];
    const float* b1  = (const float*)d_in[i + 2];
    const float* W2  = (const float*)d_in[i + 3];
    const float* b2  = (const float*)d_in[i + 4];
    float* out = (float*)d_out;

    const int scores_elems = NUMG * 1024;
    const int pairs_elems  = NUMG * 1024 * 2;
    int write_pairs = (out_size >= scores_elems + pairs_elems) ? 1 : 0;

    const int DSM = 2 * 49152;   // double-buffered tiles, 96KB
    cudaFuncSetAttribute(gemm_mma_kernel,
                         cudaFuncAttributeMaxDynamicSharedMemorySize, DSM);

    gemm_mma_kernel<<<256, 256, DSM>>>(orig, ind0, ind1, W1a, W1b, b1);
    pairwise_kernel<<<512, 256>>>(W2, b2, out, write_pairs);
}

// round 16
// speedup vs baseline: 1.1755x; 1.0023x over previous
#include <cuda_runtime.h>
#include <cuda_fp16.h>
#include <cstdint>

// orig_fea [256, 300, 256] f32; ind0/ind1 [32,32,4] i32; W1a/W1b [256,256];
// b1[256]; W2[256,1]; b2[1]. L=128, pool=1200.
#define LN   128
#define DD   256
#define HH   256
#define NUMG 32
#define BAG  300

// Scratch: h0/h1 transposed: [side][n][h][a]  (8 MB)
__device__ float g_hT[2][NUMG][HH][LN];

// ============================ helpers ============================
__device__ __forceinline__ uint32_t smem_u32(const void* p) {
    uint32_t a;
    asm("{ .reg .u64 t; cvta.to.shared.u64 t, %1; cvt.u32.u64 %0, t; }"
        : "=r"(a) : "l"(p));
    return a;
}
// f32 pair -> f16x2 (low half = x0); also return rounded-back values as f32
__device__ __forceinline__ uint32_t f16pair(float x0, float x1, float& r0, float& r1) {
    __half2 h = __floats2half2_rn(x0, x1);
    r0 = __low2float(h);
    r1 = __high2float(h);
    return *(uint32_t*)&h;
}
__device__ __forceinline__ uint32_t f16pair_n(float x0, float x1) {
    __half2 h = __floats2half2_rn(x0, x1);
    return *(uint32_t*)&h;
}
__device__ __forceinline__ void ldsm4(uint32_t* r, uint32_t addr) {
    asm volatile("ldmatrix.sync.aligned.m8n8.x4.shared.b16 {%0,%1,%2,%3}, [%4];"
        : "=r"(r[0]), "=r"(r[1]), "=r"(r[2]), "=r"(r[3]) : "r"(addr));
}
__device__ __forceinline__ void ldsm4t(uint32_t* r, uint32_t addr) {
    asm volatile("ldmatrix.sync.aligned.m8n8.x4.trans.shared.b16 {%0,%1,%2,%3}, [%4];"
        : "=r"(r[0]), "=r"(r[1]), "=r"(r[2]), "=r"(r[3]) : "r"(addr));
}
__device__ __forceinline__ void mma16816h(float* d, const uint32_t* a,
                                          uint32_t b0, uint32_t b1) {
    asm volatile("mma.sync.aligned.m16n8k16.row.col.f32.f16.f16.f32 "
        "{%0,%1,%2,%3}, {%4,%5,%6,%7}, {%8,%9}, {%0,%1,%2,%3};"
        : "+f"(d[0]), "+f"(d[1]), "+f"(d[2]), "+f"(d[3])
        : "r"(a[0]), "r"(a[1]), "r"(a[2]), "r"(a[3]), "r"(b0), "r"(b1));
}
// XOR swizzle: rows of 128B, 16B atoms permuted by row%8 -> conflict-free LDSM
#define SWZ(row, kb) ((row) * 128 + ((kb) ^ (((row) & 7) << 4)))

// ---------------------------------------------------------------------------
// Kernel 1: mma.sync fp16 2-term split GEMM (A = Ahi + Alo in fp16, B single
// fp16): D = Ahi*B + Alo*B. fp16's 11-bit mantissa makes the dropped A*Blo
// term ~2^-12 relative (vs bf16's 2^-9), so 2 terms suffice -> 2/3 the HMMA
// count of the bf16 3-term scheme. Register-prefetch double-buffered.
// grid 256 = side(2) x n(32) x h-quad(4). block 256 = 8 warps (4m x 2n).
// smem per buffer: Ahi 16KB + Alo 16KB + B 8KB = 40KB; x2 buffers = 80KB.
// ---------------------------------------------------------------------------
__global__ __launch_bounds__(256)
void gemm_mma_kernel(const float* __restrict__ orig,
                     const int*   __restrict__ ind0,
                     const int*   __restrict__ ind1,
                     const float* __restrict__ W1a,
                     const float* __restrict__ W1b,
                     const float* __restrict__ bias1)
{
    extern __shared__ char dsm[];
    __shared__ int rowoff[128];

    const int t = threadIdx.x, l = t & 31, w = t >> 5;
    const int b    = blockIdx.x;
    const int side = b >> 7;
    const int n    = (b >> 2) & 31;
    const int h0   = (b & 3) * 64;
    const int m0   = (w & 3) * 32;
    const int n0   = (w >> 2) * 32;
    const float* __restrict__ Wmat = side ? W1b : W1a;

    const uint32_t smb = smem_u32(dsm);
    const int BUFS = 40960;           // Ahi 0, Alo 16384, B 32768

    if (t < 128) {
        const int* __restrict__ ind = side ? ind1 : ind0;
        int p = ind[n * LN + t] + BAG * (t & 3);
        rowoff[t] = ((n * 2 + side) * 1200 + p) * DD;
    }
    __syncthreads();

    const int arow  = t >> 1;
    const int halfk = t & 1;
    const int ro    = rowoff[arow];
    const int bkr   = t >> 2;
    const int bhq   = t & 3;

    float acc[2][4][4];
#pragma unroll
    for (int mt = 0; mt < 2; mt++)
#pragma unroll
        for (int nt = 0; nt < 4; nt++)
#pragma unroll
            for (int i = 0; i < 4; i++) acc[mt][nt][i] = 0.f;

    float4 av[8], wv[4];

    auto stage_to_smem = [&](int buf) {
        char* base = dsm + buf * BUFS;
        // A: fp16 hi + lo, swizzled [a][k]
#pragma unroll
        for (int q2 = 0; q2 < 4; q2++) {
            float4 u = av[2 * q2], v = av[2 * q2 + 1];
            float r0, r1, r2, r3, r4, r5, r6, r7;
            uint32_t hp0 = f16pair(u.x, u.y, r0, r1);
            uint32_t hp1 = f16pair(u.z, u.w, r2, r3);
            uint32_t hp2 = f16pair(v.x, v.y, r4, r5);
            uint32_t hp3 = f16pair(v.z, v.w, r6, r7);
            uint32_t lp0 = f16pair_n(u.x - r0, u.y - r1);
            uint32_t lp1 = f16pair_n(u.z - r2, u.w - r3);
            uint32_t lp2 = f16pair_n(v.x - r4, v.y - r5);
            uint32_t lp3 = f16pair_n(v.z - r6, v.w - r7);
            int kb = halfk * 64 + q2 * 16;
            *(uint4*)(base + 0     + SWZ(arow, kb)) = make_uint4(hp0, hp1, hp2, hp3);
            *(uint4*)(base + 16384 + SWZ(arow, kb)) = make_uint4(lp0, lp1, lp2, lp3);
        }
        // B: single fp16 rounding, [k][h]
        uint32_t hb[8];
#pragma unroll
        for (int q2 = 0; q2 < 2; q2++) {
            float4 u = wv[2 * q2], v = wv[2 * q2 + 1];
            hb[q2 * 4 + 0] = f16pair_n(u.x, u.y);
            hb[q2 * 4 + 1] = f16pair_n(u.z, u.w);
            hb[q2 * 4 + 2] = f16pair_n(v.x, v.y);
            hb[q2 * 4 + 3] = f16pair_n(v.z, v.w);
        }
        int kb = bhq * 32;
        *(uint4*)(base + 32768 + SWZ(bkr, kb))      = make_uint4(hb[0], hb[1], hb[2], hb[3]);
        *(uint4*)(base + 32768 + SWZ(bkr, kb + 16)) = make_uint4(hb[4], hb[5], hb[6], hb[7]);
    };

    // prologue: chunk 0
    {
        const float4* ap = (const float4*)(orig + ro + 0 + halfk * 32);
#pragma unroll
        for (int q = 0; q < 8; q++) av[q] = ap[q];
        const float4* wp = (const float4*)&Wmat[(0 + bkr) * HH + h0 + bhq * 16];
#pragma unroll
        for (int q = 0; q < 4; q++) wv[q] = wp[q];
        stage_to_smem(0);
    }
    __syncthreads();

#pragma unroll 1
    for (int c = 0; c < 4; c++) {
        const int buf = c & 1;
        if (c < 3) {
            const float4* ap = (const float4*)(orig + ro + (c + 1) * 64 + halfk * 32);
#pragma unroll
            for (int q = 0; q < 8; q++) av[q] = ap[q];
            const float4* wp = (const float4*)&Wmat[((c + 1) * 64 + bkr) * HH + h0 + bhq * 16];
#pragma unroll
            for (int q = 0; q < 4; q++) wv[q] = wp[q];
        }
        const uint32_t bb = smb + buf * BUFS;
#pragma unroll
        for (int ks = 0; ks < 4; ks++) {
            const int rA  = m0 + (l & 15);
            const int kbL = ks * 32 + ((l >> 4) << 4);
            uint32_t ahi[2][4], alo[2][4], bf[2][4];
            ldsm4(ahi[0], bb + 0     + SWZ(rA, kbL));
            ldsm4(ahi[1], bb + 0     + SWZ(rA + 16, kbL));
            ldsm4(alo[0], bb + 16384 + SWZ(rA, kbL));
            ldsm4(alo[1], bb + 16384 + SWZ(rA + 16, kbL));
            const int rK = ks * 16 + (l & 15);
            const int hb2 = ((l >> 4) << 4);
            ldsm4t(bf[0], bb + 32768 + SWZ(rK, n0 * 2 + hb2));
            ldsm4t(bf[1], bb + 32768 + SWZ(rK, n0 * 2 + 32 + hb2));
#pragma unroll
            for (int mt = 0; mt < 2; mt++)
#pragma unroll
                for (int g = 0; g < 2; g++)
#pragma unroll
                    for (int s = 0; s < 2; s++) {
                        int nt = g * 2 + s;
                        mma16816h(acc[mt][nt], ahi[mt], bf[g][2 * s], bf[g][2 * s + 1]);
                        mma16816h(acc[mt][nt], alo[mt], bf[g][2 * s], bf[g][2 * s + 1]);
                    }
        }
        if (c < 3) {
            stage_to_smem(buf ^ 1);
            __syncthreads();
        }
    }

    const int g    = l >> 2;
    const int tid4 = l & 3;
#pragma unroll
    for (int mt = 0; mt < 2; mt++) {
        int ag = m0 + mt * 16 + g;
#pragma unroll
        for (int nt = 0; nt < 4; nt++) {
            int hg = h0 + n0 + nt * 8 + tid4 * 2;
            float bv0 = 0.f, bv1 = 0.f;
            if (side == 0) { bv0 = __ldg(&bias1[hg]); bv1 = __ldg(&bias1[hg + 1]); }
            g_hT[side][n][hg    ][ag    ] = acc[mt][nt][0] + bv0;
            g_hT[side][n][hg + 1][ag    ] = acc[mt][nt][1] + bv1;
            g_hT[side][n][hg    ][ag + 8] = acc[mt][nt][2] + bv0;
            g_hT[side][n][hg + 1][ag + 8] = acc[mt][nt][3] + bv1;
        }
    }
}

// ---------------------------------------------------------------------------
// Kernel 2: separable split (UNCHANGED from R14 winner, 21.8us):
// relu(s)*w = s*(w/2) + |s|*(w/2); pairwise loop only accumulates |s|*(w/2).
// grid 512 = n(32) x a-tile(8, 16 a) x b-tile(2, 64 b); block 256.
// ---------------------------------------------------------------------------
__global__ __launch_bounds__(256)
void pairwise_kernel(const float* __restrict__ W2,
                     const float* __restrict__ b2,
                     float* __restrict__ out,
                     int write_pairs)
{
    const int bid = blockIdx.x;
    const int n   = bid >> 4;
    const int at  = (bid >> 1) & 7;
    const int bt  = bid & 1;
    const int a0  = at * 16;
    const int b0  = bt * 64;
    const int t   = threadIdx.x;
    const int l   = t & 31;
    const int w   = t >> 5;
    const int tx  = l & 7;
    const int ty  = l >> 3;
    const int w4  = w * 4;

    __shared__ float4 xs4[256][4];
    __shared__ float4 ys4[2][32][16];
    __shared__ float  ws[256];
    __shared__ float  red[8][64];
    __shared__ float  syq[4][64];
    __shared__ float  sxq[4][16];

#pragma unroll
    for (int r = 0; r < 4; r++) {
        int id = t + 256 * r;
        int hh = id >> 2, q = id & 3;
        xs4[hh][q] = *(const float4*)&g_hT[0][n][hh][a0 + q * 4];
    }
#pragma unroll
    for (int r = 0; r < 2; r++) {
        int id = t + 256 * r;
        int hh = id >> 4, q = id & 15;
        ys4[0][hh][q] = *(const float4*)&g_hT[1][n][hh][b0 + q * 4];
    }
    ws[t] = 0.5f * W2[t];
    __syncthreads();

    {
        const int bb = t & 63, qt = t >> 6;
        const float* yp = &g_hT[1][n][qt * 64][b0 + bb];
        float p0 = 0.f, p1 = 0.f, p2 = 0.f, p3 = 0.f;
        const float* wq = &ws[qt * 64];
#pragma unroll
        for (int i = 0; i < 64; i += 4) {
            p0 = fmaf(yp[(i + 0) * LN], wq[i + 0], p0);
            p1 = fmaf(yp[(i + 1) * LN], wq[i + 1], p1);
            p2 = fmaf(yp[(i + 2) * LN], wq[i + 2], p2);
            p3 = fmaf(yp[(i + 3) * LN], wq[i + 3], p3);
        }
        syq[qt][bb] = (p0 + p1) + (p2 + p3);
    }
    if (t < 64) {
        const int aa = t & 15, qt = t >> 4;
        float p0 = 0.f, p1 = 0.f;
#pragma unroll
        for (int i = 0; i < 64; i += 2) {
            int h = qt * 64 + i;
            p0 = fmaf(((const float*)&xs4[h    ][0])[aa], ws[h    ], p0);
            p1 = fmaf(((const float*)&xs4[h + 1][0])[aa], ws[h + 1], p1);
        }
        sxq[qt][aa] = p0 + p1;
    }

    float acc[4][8];
#pragma unroll
    for (int j = 0; j < 4; j++)
#pragma unroll
        for (int i = 0; i < 8; i++) acc[j][i] = 0.f;

    int buf = 0;
#pragma unroll 1
    for (int hc = 0; hc < 8; hc++) {
        float4 st[2];
        if (hc < 7) {
#pragma unroll
            for (int r = 0; r < 2; r++) {
                int id = t + 256 * r;
                int hh = id >> 4, q = id & 15;
                st[r] = *(const float4*)&g_hT[1][n][(hc + 1) * 32 + hh][b0 + q * 4];
            }
        }
#pragma unroll
        for (int u = 0; u < 4; u++) {
            const int hh = w4 + u;
            const int hs = hc * 32 + hh;
            float  wv = ws[hs];
            float4 x4 = xs4[hs][ty];
            float4 ya = ys4[buf][hh][tx * 2];
            float4 yb = ys4[buf][hh][tx * 2 + 1];
            float xa[4] = {x4.x, x4.y, x4.z, x4.w};
            float yv[8] = {ya.x, ya.y, ya.z, ya.w, yb.x, yb.y, yb.z, yb.w};
#pragma unroll
            for (int j = 0; j < 4; j++)
#pragma unroll
                for (int i = 0; i < 8; i++) {
                    float s = xa[j] + yv[i];
                    acc[j][i] = fmaf(fabsf(s), wv, acc[j][i]);
                }
        }
        if (hc < 7) {
            int nb = buf ^ 1;
#pragma unroll
            for (int r = 0; r < 2; r++) {
                int id = t + 256 * r;
                int hh = id >> 4, q = id & 15;
                ys4[nb][hh][q] = st[r];
            }
            __syncthreads();
            buf = nb;
        }
    }

    float s0 = 0.f, s1 = 0.f;
#pragma unroll
    for (int j = 0; j < 4; j++) {
        s0 += acc[j][0] + acc[j][1] + acc[j][2] + acc[j][3];
        s1 += acc[j][4] + acc[j][5] + acc[j][6] + acc[j][7];
    }
    red[w][(ty * 8 + tx) * 2    ] = s0;
    red[w][(ty * 8 + tx) * 2 + 1] = s1;
    __syncthreads();

    if (t < 64) {
        const int m  = t >> 4;
        const int li = t & 15;
        const int slot = (m * 8 + (li >> 1)) * 2 + (li & 1);
        float s = 0.f;
#pragma unroll
        for (int g = 0; g < 8; g++) s += red[g][slot];
        float sep = 0.f;
#pragma unroll
        for (int qt = 0; qt < 4; qt++)
#pragma unroll
            for (int p = 0; p < 4; p++)
                sep += sxq[qt][m * 4 + p] + syq[qt][li * 4 + p];
        s += 4.f * sep;
        s += 16.f * __ldg(b2);
        out[n * 1024 + (at * 4 + m) * 32 + bt * 16 + li] = s;
    }

    if (write_pairs && t < 128) {
        int id    = bid * 128 + t;
        int pi    = id >> 1;
        int which = id & 1;
        int idx   = pi & 1023;
        int v = which ? (idx & 31) : (idx >> 5);
        out[NUMG * 1024 + id] = (float)v;
    }
}

extern "C" void kernel_launch(void* const* d_in, const int* in_sizes, int n_in,
                              void* d_out, int out_size)
{
    const float* orig = (const float*)d_in[0];
    const int*   ind0 = (const int*)d_in[1];
    const int*   ind1 = (const int*)d_in[2];
    int i = 3;
    if (n_in >= 9 && in_sizes[3] == 1) i = 4;   // scalar k materialized
    const float* W1a = (const float*)d_in[i + 0];
    const float* W1b = (const float*)d_in[i + 1];
    const float* b1  = (const float*)d_in[i + 2];
    const float* W2  = (const float*)d_in[i + 3];
    const float* b2  = (const float*)d_in[i + 4];
    float* out = (float*)d_out;

    const int scores_elems = NUMG * 1024;
    const int pairs_elems  = NUMG * 1024 * 2;
    int write_pairs = (out_size >= scores_elems + pairs_elems) ? 1 : 0;

    const int DSM = 2 * 40960;   // double-buffered fp16 tiles, 80KB
    cudaFuncSetAttribute(gemm_mma_kernel,
                         cudaFuncAttributeMaxDynamicSharedMemorySize, DSM);

    gemm_mma_kernel<<<256, 256, DSM>>>(orig, ind0, ind1, W1a, W1b, b1);
    pairwise_kernel<<<512, 256>>>(W2, b2, out, write_pairs);
}

// round 17
// speedup vs baseline: 1.2461x; 1.0601x over previous
#include <cuda_runtime.h>
#include <cuda_fp16.h>
#include <cstdint>

// orig_fea [256, 300, 256] f32; ind0/ind1 [32,32,4] i32; W1a/W1b [256,256];
// b1[256]; W2[256,1]; b2[1]. L=128, pool=1200.
#define LN   128
#define DD   256
#define HH   256
#define NUMG 32
#define BAG  300

// Scratch: h0/h1 transposed: [side][n][h][a]  (8 MB)
__device__ float g_hT[2][NUMG][HH][LN];

// ============================ helpers ============================
__device__ __forceinline__ uint32_t smem_u32(const void* p) {
    uint32_t a;
    asm("{ .reg .u64 t; cvta.to.shared.u64 t, %1; cvt.u32.u64 %0, t; }"
        : "=r"(a) : "l"(p));
    return a;
}
__device__ __forceinline__ uint32_t f16pair_n(float x0, float x1) {
    __half2 h = __floats2half2_rn(x0, x1);
    return *(uint32_t*)&h;
}
__device__ __forceinline__ void ldsm4(uint32_t* r, uint32_t addr) {
    asm volatile("ldmatrix.sync.aligned.m8n8.x4.shared.b16 {%0,%1,%2,%3}, [%4];"
        : "=r"(r[0]), "=r"(r[1]), "=r"(r[2]), "=r"(r[3]) : "r"(addr));
}
__device__ __forceinline__ void ldsm4t(uint32_t* r, uint32_t addr) {
    asm volatile("ldmatrix.sync.aligned.m8n8.x4.trans.shared.b16 {%0,%1,%2,%3}, [%4];"
        : "=r"(r[0]), "=r"(r[1]), "=r"(r[2]), "=r"(r[3]) : "r"(addr));
}
__device__ __forceinline__ void mma16816h(float* d, const uint32_t* a,
                                          uint32_t b0, uint32_t b1) {
    asm volatile("mma.sync.aligned.m16n8k16.row.col.f32.f16.f16.f32 "
        "{%0,%1,%2,%3}, {%4,%5,%6,%7}, {%8,%9}, {%0,%1,%2,%3};"
        : "+f"(d[0]), "+f"(d[1]), "+f"(d[2]), "+f"(d[3])
        : "r"(a[0]), "r"(a[1]), "r"(a[2]), "r"(a[3]), "r"(b0), "r"(b1));
}
// XOR swizzle: rows of 128B, 16B atoms permuted by row%8 -> conflict-free LDSM
#define SWZ(row, kb) ((row) * 128 + ((kb) ^ (((row) & 7) << 4)))

// ---------------------------------------------------------------------------
// Kernel 1: pure fp16 mma.sync GEMM (single term: round(A)*round(B)).
// rel_err budget: A-round + B-round each ~1.5e-4 at endpoint (B-only measured
// 1.483e-4 in R16) -> combined ~2.1e-4, 4.8x under the 1e-3 gate.
// grid 512 = side(2) x n(32) x hquad(4) x ahalf(2): 64 a x 64 h per block ->
// 3.5 blocks/SM (was 1.7), balanced wave. Register-prefetch double-buffered.
// block 256 = 8 warps (4m x 2n): warp tile 16a x 32h; 64 HMMA per warp.
// smem: A 8KB + B 8KB per buffer; x2 = 32KB.
// ---------------------------------------------------------------------------
__global__ __launch_bounds__(256)
void gemm_mma_kernel(const float* __restrict__ orig,
                     const int*   __restrict__ ind0,
                     const int*   __restrict__ ind1,
                     const float* __restrict__ W1a,
                     const float* __restrict__ W1b,
                     const float* __restrict__ bias1)
{
    extern __shared__ char dsm[];
    __shared__ int rowoff[64];

    const int t = threadIdx.x, l = t & 31, w = t >> 5;
    const int b    = blockIdx.x;
    const int side = b >> 8;
    const int n    = (b >> 3) & 31;
    const int h0   = ((b >> 1) & 3) * 64;
    const int ah   = b & 1;
    const int m0   = (w & 3) * 16;
    const int n0   = (w >> 2) * 32;
    const float* __restrict__ Wmat = side ? W1b : W1a;

    const uint32_t smb = smem_u32(dsm);
    const int BUFS = 16384;           // A 0 (8KB), B 8192 (8KB)

    if (t < 64) {
        const int* __restrict__ ind = side ? ind1 : ind0;
        int a = ah * 64 + t;
        int p = ind[n * LN + a] + BAG * (a & 3);
        rowoff[t] = ((n * 2 + side) * 1200 + p) * DD;
    }
    __syncthreads();

    const int arow = t >> 2;          // 0..63 (a row within block)
    const int aq   = t & 3;           // quarter of row: 16 floats
    const int ro   = rowoff[arow];
    const int bkr  = t >> 2;          // B k-row 0..63
    const int bhq  = t & 3;           // 16-h group

    float acc[4][4];                  // [nt][frag]
#pragma unroll
    for (int nt = 0; nt < 4; nt++)
#pragma unroll
        for (int i = 0; i < 4; i++) acc[nt][i] = 0.f;

    float4 av[4], wv[4];

    auto stage_to_smem = [&](int buf) {
        char* base = dsm + buf * BUFS;
        uint32_t ha[8], hb[8];
#pragma unroll
        for (int q2 = 0; q2 < 2; q2++) {
            float4 u = av[2 * q2], v = av[2 * q2 + 1];
            ha[q2 * 4 + 0] = f16pair_n(u.x, u.y);
            ha[q2 * 4 + 1] = f16pair_n(u.z, u.w);
            ha[q2 * 4 + 2] = f16pair_n(v.x, v.y);
            ha[q2 * 4 + 3] = f16pair_n(v.z, v.w);
            float4 p = wv[2 * q2], q = wv[2 * q2 + 1];
            hb[q2 * 4 + 0] = f16pair_n(p.x, p.y);
            hb[q2 * 4 + 1] = f16pair_n(p.z, p.w);
            hb[q2 * 4 + 2] = f16pair_n(q.x, q.y);
            hb[q2 * 4 + 3] = f16pair_n(q.z, q.w);
        }
        int ka = aq * 32;
        *(uint4*)(base + 0 + SWZ(arow, ka))      = make_uint4(ha[0], ha[1], ha[2], ha[3]);
        *(uint4*)(base + 0 + SWZ(arow, ka + 16)) = make_uint4(ha[4], ha[5], ha[6], ha[7]);
        int kb = bhq * 32;
        *(uint4*)(base + 8192 + SWZ(bkr, kb))      = make_uint4(hb[0], hb[1], hb[2], hb[3]);
        *(uint4*)(base + 8192 + SWZ(bkr, kb + 16)) = make_uint4(hb[4], hb[5], hb[6], hb[7]);
    };

    // prologue: chunk 0
    {
        const float4* ap = (const float4*)(orig + ro + aq * 16);
#pragma unroll
        for (int q = 0; q < 4; q++) av[q] = ap[q];
        const float4* wp = (const float4*)&Wmat[bkr * HH + h0 + bhq * 16];
#pragma unroll
        for (int q = 0; q < 4; q++) wv[q] = wp[q];
        stage_to_smem(0);
    }
    __syncthreads();

#pragma unroll 1
    for (int c = 0; c < 4; c++) {
        const int buf = c & 1;
        if (c < 3) {
            const float4* ap = (const float4*)(orig + ro + (c + 1) * 64 + aq * 16);
#pragma unroll
            for (int q = 0; q < 4; q++) av[q] = ap[q];
            const float4* wp = (const float4*)&Wmat[((c + 1) * 64 + bkr) * HH + h0 + bhq * 16];
#pragma unroll
            for (int q = 0; q < 4; q++) wv[q] = wp[q];
        }
        const uint32_t bb = smb + buf * BUFS;
#pragma unroll
        for (int ks = 0; ks < 4; ks++) {
            const int rA  = m0 + (l & 15);
            const int kbL = ks * 32 + ((l >> 4) << 4);
            uint32_t af[4], bf[2][4];
            ldsm4(af, bb + 0 + SWZ(rA, kbL));
            const int rK  = ks * 16 + (l & 15);
            const int hb2 = ((l >> 4) << 4);
            ldsm4t(bf[0], bb + 8192 + SWZ(rK, n0 * 2 + hb2));
            ldsm4t(bf[1], bb + 8192 + SWZ(rK, n0 * 2 + 32 + hb2));
#pragma unroll
            for (int g = 0; g < 2; g++)
#pragma unroll
                for (int s = 0; s < 2; s++)
                    mma16816h(acc[g * 2 + s], af, bf[g][2 * s], bf[g][2 * s + 1]);
        }
        if (c < 3) {
            stage_to_smem(buf ^ 1);
            __syncthreads();
        }
    }

    // epilogue: write transposed to g_hT (+b1 on side 0)
    const int g    = l >> 2;
    const int tid4 = l & 3;
    const int ag0  = ah * 64 + m0 + g;
#pragma unroll
    for (int nt = 0; nt < 4; nt++) {
        int hg = h0 + n0 + nt * 8 + tid4 * 2;
        float bv0 = 0.f, bv1 = 0.f;
        if (side == 0) { bv0 = __ldg(&bias1[hg]); bv1 = __ldg(&bias1[hg + 1]); }
        g_hT[side][n][hg    ][ag0    ] = acc[nt][0] + bv0;
        g_hT[side][n][hg + 1][ag0    ] = acc[nt][1] + bv1;
        g_hT[side][n][hg    ][ag0 + 8] = acc[nt][2] + bv0;
        g_hT[side][n][hg + 1][ag0 + 8] = acc[nt][3] + bv1;
    }
}

// ---------------------------------------------------------------------------
// Kernel 2: separable split (UNCHANGED from R14/R16 winner, 21.9us):
// relu(s)*w = s*(w/2) + |s|*(w/2); pairwise loop only accumulates |s|*(w/2).
// grid 512 = n(32) x a-tile(8, 16 a) x b-tile(2, 64 b); block 256.
// ---------------------------------------------------------------------------
__global__ __launch_bounds__(256)
void pairwise_kernel(const float* __restrict__ W2,
                     const float* __restrict__ b2,
                     float* __restrict__ out,
                     int write_pairs)
{
    const int bid = blockIdx.x;
    const int n   = bid >> 4;
    const int at  = (bid >> 1) & 7;
    const int bt  = bid & 1;
    const int a0  = at * 16;
    const int b0  = bt * 64;
    const int t   = threadIdx.x;
    const int l   = t & 31;
    const int w   = t >> 5;
    const int tx  = l & 7;
    const int ty  = l >> 3;
    const int w4  = w * 4;

    __shared__ float4 xs4[256][4];
    __shared__ float4 ys4[2][32][16];
    __shared__ float  ws[256];
    __shared__ float  red[8][64];
    __shared__ float  syq[4][64];
    __shared__ float  sxq[4][16];

#pragma unroll
    for (int r = 0; r < 4; r++) {
        int id = t + 256 * r;
        int hh = id >> 2, q = id & 3;
        xs4[hh][q] = *(const float4*)&g_hT[0][n][hh][a0 + q * 4];
    }
#pragma unroll
    for (int r = 0; r < 2; r++) {
        int id = t + 256 * r;
        int hh = id >> 4, q = id & 15;
        ys4[0][hh][q] = *(const float4*)&g_hT[1][n][hh][b0 + q * 4];
    }
    ws[t] = 0.5f * W2[t];
    __syncthreads();

    {
        const int bb = t & 63, qt = t >> 6;
        const float* yp = &g_hT[1][n][qt * 64][b0 + bb];
        float p0 = 0.f, p1 = 0.f, p2 = 0.f, p3 = 0.f;
        const float* wq = &ws[qt * 64];
#pragma unroll
        for (int i = 0; i < 64; i += 4) {
            p0 = fmaf(yp[(i + 0) * LN], wq[i + 0], p0);
            p1 = fmaf(yp[(i + 1) * LN], wq[i + 1], p1);
            p2 = fmaf(yp[(i + 2) * LN], wq[i + 2], p2);
            p3 = fmaf(yp[(i + 3) * LN], wq[i + 3], p3);
        }
        syq[qt][bb] = (p0 + p1) + (p2 + p3);
    }
    if (t < 64) {
        const int aa = t & 15, qt = t >> 4;
        float p0 = 0.f, p1 = 0.f;
#pragma unroll
        for (int i = 0; i < 64; i += 2) {
            int h = qt * 64 + i;
            p0 = fmaf(((const float*)&xs4[h    ][0])[aa], ws[h    ], p0);
            p1 = fmaf(((const float*)&xs4[h + 1][0])[aa], ws[h + 1], p1);
        }
        sxq[qt][aa] = p0 + p1;
    }

    float acc[4][8];
#pragma unroll
    for (int j = 0; j < 4; j++)
#pragma unroll
        for (int i = 0; i < 8; i++) acc[j][i] = 0.f;

    int buf = 0;
#pragma unroll 1
    for (int hc = 0; hc < 8; hc++) {
        float4 st[2];
        if (hc < 7) {
#pragma unroll
            for (int r = 0; r < 2; r++) {
                int id = t + 256 * r;
                int hh = id >> 4, q = id & 15;
                st[r] = *(const float4*)&g_hT[1][n][(hc + 1) * 32 + hh][b0 + q * 4];
            }
        }
#pragma unroll
        for (int u = 0; u < 4; u++) {
            const int hh = w4 + u;
            const int hs = hc * 32 + hh;
            float  wv = ws[hs];
            float4 x4 = xs4[hs][ty];
            float4 ya = ys4[buf][hh][tx * 2];
            float4 yb = ys4[buf][hh][tx * 2 + 1];
            float xa[4] = {x4.x, x4.y, x4.z, x4.w};
            float yv[8] = {ya.x, ya.y, ya.z, ya.w, yb.x, yb.y, yb.z, yb.w};
#pragma unroll
            for (int j = 0; j < 4; j++)
#pragma unroll
                for (int i = 0; i < 8; i++) {
                    float s = xa[j] + yv[i];
                    acc[j][i] = fmaf(fabsf(s), wv, acc[j][i]);
                }
        }
        if (hc < 7) {
            int nb = buf ^ 1;
#pragma unroll
            for (int r = 0; r < 2; r++) {
                int id = t + 256 * r;
                int hh = id >> 4, q = id & 15;
                ys4[nb][hh][q] = st[r];
            }
            __syncthreads();
            buf = nb;
        }
    }

    float s0 = 0.f, s1 = 0.f;
#pragma unroll
    for (int j = 0; j < 4; j++) {
        s0 += acc[j][0] + acc[j][1] + acc[j][2] + acc[j][3];
        s1 += acc[j][4] + acc[j][5] + acc[j][6] + acc[j][7];
    }
    red[w][(ty * 8 + tx) * 2    ] = s0;
    red[w][(ty * 8 + tx) * 2 + 1] = s1;
    __syncthreads();

    if (t < 64) {
        const int m  = t >> 4;
        const int li = t & 15;
        const int slot = (m * 8 + (li >> 1)) * 2 + (li & 1);
        float s = 0.f;
#pragma unroll
        for (int g = 0; g < 8; g++) s += red[g][slot];
        float sep = 0.f;
#pragma unroll
        for (int qt = 0; qt < 4; qt++)
#pragma unroll
            for (int p = 0; p < 4; p++)
                sep += sxq[qt][m * 4 + p] + syq[qt][li * 4 + p];
        s += 4.f * sep;
        s += 16.f * __ldg(b2);
        out[n * 1024 + (at * 4 + m) * 32 + bt * 16 + li] = s;
    }

    if (write_pairs && t < 128) {
        int id    = bid * 128 + t;
        int pi    = id >> 1;
        int which = id & 1;
        int idx   = pi & 1023;
        int v = which ? (idx & 31) : (idx >> 5);
        out[NUMG * 1024 + id] = (float)v;
    }
}

extern "C" void kernel_launch(void* const* d_in, const int* in_sizes, int n_in,
                              void* d_out, int out_size)
{
    const float* orig = (const float*)d_in[0];
    const int*   ind0 = (const int*)d_in[1];
    const int*   ind1 = (const int*)d_in[2];
    int i = 3;
    if (n_in >= 9 && in_sizes[3] == 1) i = 4;   // scalar k materialized
    const float* W1a = (const float*)d_in[i + 0];
    const float* W1b = (const float*)d_in[i + 1];
    const float* b1  = (const float*)d_in[i + 2];
    const float* W2  = (const float*)d_in[i + 3];
    const float* b2  = (const float*)d_in[i + 4];
    float* out = (float*)d_out;

    const int scores_elems = NUMG * 1024;
    const int pairs_elems  = NUMG * 1024 * 2;
    int write_pairs = (out_size >= scores_elems + pairs_elems) ? 1 : 0;

    const int DSM = 2 * 16384;   // double-buffered fp16 tiles, 32KB
    cudaFuncSetAttribute(gemm_mma_kernel,
                         cudaFuncAttributeMaxDynamicSharedMemorySize, DSM);

    gemm_mma_kernel<<<512, 256, DSM>>>(orig, ind0, ind1, W1a, W1b, b1);
    pairwise_kernel<<<512, 256>>>(W2, b2, out, write_pairs);
}